// round 1
// baseline (speedup 1.0000x reference)
#include <cuda_runtime.h>
#include <math.h>

#define BB 8
#define NN 256
#define CC 128
#define TT 64
#define HH 4
#define GG 12
#define DD 32
#define FEPS 1e-6f

// ---------------- scratch (device globals; no allocation allowed) ----------------
__device__ float g_P[CC * GG];     // (Wtk @ Wrel^T)/sqrt(C)   [cc][g]
__device__ float g_p0[GG];         // (btk @ Wrel^T)/sqrt(C)
__device__ float g_pc[CC];         // (Wtk @ brel)/sqrt(C)
__device__ float g_pc0[1];         // (btk . brel)/sqrt(C)
__device__ float g_Qm[CC * HH];    // Wtv @ Wbias              [cc][h]
__device__ float g_q0[HH];         // btv @ Wbias
__device__ float g_Wrb[GG * HH];   // Wrel @ Wbias             [g][h]
__device__ float g_cb[HH];         // brel @ Wbias + bbias
__device__ float g_M[BB * GG * TT];   // per-batch score matrix [b][g][t]
__device__ float g_c0[BB * TT];       // per-batch score const  [b][t]
__device__ float g_Vb[BB * TT * HH];  // v_txt @ Wbias          [b][t][h]
__device__ float g_q[BB * HH * NN * DD];
__device__ float g_k[BB * HH * NN * DD];
__device__ float g_v[BB * HH * NN * DD];
__device__ float g_sizes[BB * NN * 3];

// ---------------- kernel 0: tiny weight-combo precompute ----------------
__global__ void k_combos(const float* __restrict__ Wtk, const float* __restrict__ btk,
                         const float* __restrict__ Wtv, const float* __restrict__ btv,
                         const float* __restrict__ Wrel, const float* __restrict__ brel,
                         const float* __restrict__ Wbias, const float* __restrict__ bbias)
{
    const float isC = 0.08838834764831845f;  // 1/sqrt(128)
    int idx = blockIdx.x * blockDim.x + threadIdx.x;
    if (idx < 1536) {
        int cc = idx / 12, g = idx % 12;
        float s = 0.f;
        for (int c = 0; c < CC; c++) s += Wtk[cc * CC + c] * Wrel[g * CC + c];
        g_P[idx] = s * isC;
    } else if (idx < 1548) {
        int g = idx - 1536;
        float s = 0.f;
        for (int c = 0; c < CC; c++) s += btk[c] * Wrel[g * CC + c];
        g_p0[g] = s * isC;
    } else if (idx < 1676) {
        int cc = idx - 1548;
        float s = 0.f;
        for (int c = 0; c < CC; c++) s += Wtk[cc * CC + c] * brel[c];
        g_pc[cc] = s * isC;
    } else if (idx == 1676) {
        float s = 0.f;
        for (int c = 0; c < CC; c++) s += btk[c] * brel[c];
        g_pc0[0] = s * isC;
    } else if (idx < 2189) {
        int q = idx - 1677; int cc = q / 4, h = q % 4;
        float s = 0.f;
        for (int c = 0; c < CC; c++) s += Wtv[cc * CC + c] * Wbias[c * HH + h];
        g_Qm[cc * HH + h] = s;
    } else if (idx < 2193) {
        int h = idx - 2189;
        float s = 0.f;
        for (int c = 0; c < CC; c++) s += btv[c] * Wbias[c * HH + h];
        g_q0[h] = s;
    } else if (idx < 2241) {
        int q = idx - 2193; int g = q / 4, h = q % 4;
        float s = 0.f;
        for (int c = 0; c < CC; c++) s += Wrel[g * CC + c] * Wbias[c * HH + h];
        g_Wrb[q] = s;
    } else if (idx < 2245) {
        int h = idx - 2241;
        float s = 0.f;
        for (int c = 0; c < CC; c++) s += brel[c] * Wbias[c * HH + h];
        g_cb[h] = s + bbias[h];
    }
}

// ---------------- kernel 1: project lang tokens -> M, c0, Vb ----------------
__global__ __launch_bounds__(128) void k_lang(const float* __restrict__ lang)
{
    const int bt = blockIdx.x;            // 0 .. B*T-1
    const int b = bt >> 6, t = bt & 63;
    const int tid = threadIdx.x;
    __shared__ float L[CC];
    L[tid] = lang[bt * CC + tid];
    __syncthreads();
    const int wid = tid >> 5, lane = tid & 31;
    for (int o = wid; o < 17; o += 4) {
        float s = 0.f;
        if (o < 12) {
            for (int c = lane; c < CC; c += 32) s += L[c] * g_P[c * GG + o];
        } else if (o == 12) {
            for (int c = lane; c < CC; c += 32) s += L[c] * g_pc[c];
        } else {
            int h = o - 13;
            for (int c = lane; c < CC; c += 32) s += L[c] * g_Qm[c * HH + h];
        }
        #pragma unroll
        for (int off = 16; off; off >>= 1) s += __shfl_xor_sync(0xffffffffu, s, off);
        if (lane == 0) {
            if (o < 12)       g_M[(b * GG + o) * TT + t] = s + g_p0[o];
            else if (o == 12) g_c0[b * TT + t] = s + g_pc0[0];
            else              g_Vb[(b * TT + t) * HH + (o - 13)] = s + g_q0[o - 13];
        }
    }
}

// ---------------- kernel 2: QKV projections + box sizes ----------------
__global__ __launch_bounds__(128) void k_qkv(
    const float* __restrict__ feat, const float* __restrict__ corners,
    const float* __restrict__ Wq, const float* __restrict__ bq,
    const float* __restrict__ Wk, const float* __restrict__ bk,
    const float* __restrict__ Wv, const float* __restrict__ bv)
{
    const int blk = blockIdx.x;           // 256 blocks x 8 rows
    const int tid = threadIdx.x;          // 128 = output channel
    const int row0 = blk * 8;
    __shared__ float F[8][CC];
    #pragma unroll
    for (int r = 0; r < 8; r++) F[r][tid] = feat[(row0 + r) * CC + tid];
    __syncthreads();
    float aq[8], ak[8], av[8];
    #pragma unroll
    for (int r = 0; r < 8; r++) { aq[r] = bq[tid]; ak[r] = bk[tid]; av[r] = bv[tid]; }
    for (int cc = 0; cc < CC; cc++) {
        float wq = Wq[cc * CC + tid], wk = Wk[cc * CC + tid], wv = Wv[cc * CC + tid];
        #pragma unroll
        for (int r = 0; r < 8; r++) {
            float f = F[r][cc];
            aq[r] += f * wq; ak[r] += f * wk; av[r] += f * wv;
        }
    }
    const int h = tid >> 5, d = tid & 31;
    #pragma unroll
    for (int r = 0; r < 8; r++) {
        int bi = row0 + r; int b = bi >> 8, i = bi & 255;
        int o = ((b * HH + h) * NN + i) * DD + d;
        g_q[o] = aq[r]; g_k[o] = ak[r]; g_v[o] = av[r];
    }
    if (tid < 24) {
        int r = tid / 3, kd = tid % 3;
        int bi = row0 + r;
        float mx = -1e30f, mn = 1e30f;
        for (int cn = 0; cn < 8; cn++) {
            float v2 = corners[(bi * 8 + cn) * 3 + kd];
            mx = fmaxf(mx, v2); mn = fminf(mn, v2);
        }
        g_sizes[bi * 3 + kd] = mx - mn;
    }
}

// ---------------- kernel 3: fused geometry + lang-attn bias + attention + out proj ----------------
__global__ __launch_bounds__(256, 2) void k_main(
    const float* __restrict__ centers,
    const float* __restrict__ Wo,
    const float* __restrict__ bo,
    float* __restrict__ out)
{
    const int i = blockIdx.x;
    const int b = blockIdx.y;
    const int tid = threadIdx.x;

    __shared__ float4 sM4[GG * 16];   // [g][t/4]
    __shared__ float  sC0[TT];
    __shared__ float4 sVb4[TT];       // [t] -> h0..h3
    __shared__ float  sWrb[GG * HH];
    __shared__ float  sCb[HH];
    __shared__ float4 sQ4[HH * 8];    // q row for i, [h][d/4]
    __shared__ float  sCi[3], sSi[3];
    __shared__ float4 sE4[NN];        // exp(logit - max) per j, 4 heads
    __shared__ float  sRedM[8 * HH];
    __shared__ float  sRedS[8 * HH];
    __shared__ float  sO[2][CC];
    __shared__ float  sOF[CC];

    float* sM  = (float*)sM4;
    float* sVb = (float*)sVb4;
    float* sQ  = (float*)sQ4;
    float* sE  = (float*)sE4;

    {
        const float* Mb = g_M + b * (GG * TT);
        for (int x = tid; x < GG * TT; x += 256) sM[x] = Mb[x];
        if (tid < TT) sC0[tid] = g_c0[b * TT + tid];
        sVb[tid] = g_Vb[b * TT * HH + tid];       // 256 elements
        if (tid < GG * HH) sWrb[tid] = g_Wrb[tid];
        if (tid < HH) sCb[tid] = g_cb[tid];
        if (tid < CC) {
            int h = tid >> 5, d = tid & 31;
            sQ[tid] = g_q[((b * HH + h) * NN + i) * DD + d];
        }
        if (tid < 3) {
            sCi[tid] = centers[(b * NN + i) * 3 + tid];
            sSi[tid] = g_sizes[(b * NN + i) * 3 + tid];
        }
    }
    __syncthreads();

    const int j = tid;
    float cjx = centers[(b * NN + j) * 3 + 0];
    float cjy = centers[(b * NN + j) * 3 + 1];
    float cjz = centers[(b * NN + j) * 3 + 2];
    float rx = cjx - sCi[0], ry = cjy - sCi[1], rz = cjz - sCi[2];
    float dist  = sqrtf(rx * rx + ry * ry + rz * rz);
    float horiz = sqrtf(rx * rx + ry * ry);
    float dl = logf(dist + FEPS);
    float ce = rz / (dist + FEPS);
    float sj0 = g_sizes[(b * NN + j) * 3 + 0];
    float sj1 = g_sizes[(b * NN + j) * 3 + 1];
    float sj2 = g_sizes[(b * NN + j) * 3 + 2];
    float geom[GG];
    geom[0] = rx; geom[1] = ry; geom[2] = rz;
    geom[3] = dl; geom[4] = horiz; geom[5] = ce;
    geom[6] = sj0 - sSi[0]; geom[7] = sj1 - sSi[1]; geom[8] = sj2 - sSi[2];
    geom[9]  = sj0 / (sSi[0] + FEPS);
    geom[10] = sj1 / (sSi[1] + FEPS);
    geom[11] = sj2 / (sSi[2] + FEPS);

    // scores over 64 lang tokens: sc[t] = c0[t] + sum_g geom[g]*M[g][t]
    float sc[TT];
    #pragma unroll
    for (int t = 0; t < TT; t++) sc[t] = sC0[t];
    #pragma unroll
    for (int g = 0; g < GG; g++) {
        float gv = geom[g];
        #pragma unroll
        for (int t4 = 0; t4 < 16; t4++) {
            float4 m = sM4[g * 16 + t4];
            sc[t4 * 4 + 0] += gv * m.x;
            sc[t4 * 4 + 1] += gv * m.y;
            sc[t4 * 4 + 2] += gv * m.z;
            sc[t4 * 4 + 3] += gv * m.w;
        }
    }
    // token softmax (in-thread)
    float mx = sc[0];
    #pragma unroll
    for (int t = 1; t < TT; t++) mx = fmaxf(mx, sc[t]);
    float sum = 0.f;
    #pragma unroll
    for (int t = 0; t < TT; t++) { float e = __expf(sc[t] - mx); sc[t] = e; sum += e; }
    float inv = 1.0f / sum;

    // bias per head: geom@Wrb + cb + (alpha @ Vb)
    float bh0 = sCb[0], bh1 = sCb[1], bh2 = sCb[2], bh3 = sCb[3];
    #pragma unroll
    for (int g = 0; g < GG; g++) {
        float gv = geom[g];
        bh0 += gv * sWrb[g * 4 + 0];
        bh1 += gv * sWrb[g * 4 + 1];
        bh2 += gv * sWrb[g * 4 + 2];
        bh3 += gv * sWrb[g * 4 + 3];
    }
    float a0 = 0.f, a1 = 0.f, a2 = 0.f, a3 = 0.f;
    #pragma unroll
    for (int t = 0; t < TT; t++) {
        float4 vb = sVb4[t];
        float e = sc[t];
        a0 += e * vb.x; a1 += e * vb.y; a2 += e * vb.z; a3 += e * vb.w;
    }
    bh0 += a0 * inv; bh1 += a1 * inv; bh2 += a2 * inv; bh3 += a3 * inv;
    float bhv[HH] = {bh0, bh1, bh2, bh3};

    // QK logits
    float lg[HH];
    #pragma unroll
    for (int h = 0; h < HH; h++) {
        const float4* kp = (const float4*)(g_k + (((size_t)(b * HH + h) * NN + j) * DD));
        float dot = 0.f;
        #pragma unroll
        for (int d4 = 0; d4 < 8; d4++) {
            float4 kv = kp[d4];
            float4 qv = sQ4[h * 8 + d4];
            dot += kv.x * qv.x + kv.y * qv.y + kv.z * qv.z + kv.w * qv.w;
        }
        lg[h] = dot * 0.17677669529663687f + bhv[h];   // 1/sqrt(32)
    }

    // block softmax over j (256) per head
    const int wid = tid >> 5, lane = tid & 31;
    float m4[HH];
    #pragma unroll
    for (int h = 0; h < HH; h++) m4[h] = lg[h];
    #pragma unroll
    for (int off = 16; off; off >>= 1) {
        #pragma unroll
        for (int h = 0; h < HH; h++)
            m4[h] = fmaxf(m4[h], __shfl_xor_sync(0xffffffffu, m4[h], off));
    }
    if (lane == 0) {
        #pragma unroll
        for (int h = 0; h < HH; h++) sRedM[wid * 4 + h] = m4[h];
    }
    __syncthreads();
    float hmax[HH];
    #pragma unroll
    for (int h = 0; h < HH; h++) {
        float m = sRedM[h];
        #pragma unroll
        for (int w = 1; w < 8; w++) m = fmaxf(m, sRedM[w * 4 + h]);
        hmax[h] = m;
    }
    float e4[HH], s4[HH];
    #pragma unroll
    for (int h = 0; h < HH; h++) { e4[h] = __expf(lg[h] - hmax[h]); s4[h] = e4[h]; }
    sE4[tid] = make_float4(e4[0], e4[1], e4[2], e4[3]);
    #pragma unroll
    for (int off = 16; off; off >>= 1) {
        #pragma unroll
        for (int h = 0; h < HH; h++)
            s4[h] += __shfl_xor_sync(0xffffffffu, s4[h], off);
    }
    __syncthreads();   // sRedM reads done
    if (lane == 0) {
        #pragma unroll
        for (int h = 0; h < HH; h++) sRedS[wid * 4 + h] = s4[h];
    }
    __syncthreads();

    // attention output: each (h,d) pair handled by 2 threads (j halves)
    const int pair = tid & 127;
    const int half = tid >> 7;
    {
        const int h = pair >> 5, d = pair & 31;
        const float* vp = g_v + ((size_t)(b * HH + h) * NN + half * 128) * DD + d;
        float acc = 0.f;
        #pragma unroll 8
        for (int jj = 0; jj < 128; jj++)
            acc += sE[(half * 128 + jj) * 4 + h] * vp[jj * DD];
        sO[half][pair] = acc;
    }
    __syncthreads();
    if (tid < CC) {
        int hh = tid >> 5;
        float s = sRedS[hh];
        #pragma unroll
        for (int w = 1; w < 8; w++) s += sRedS[w * 4 + hh];
        sOF[tid] = (sO[0][tid] + sO[1][tid]) / s;
    }
    __syncthreads();

    // output projection: out[b,i,:] = sOF @ Wo + bo
    {
        const int c = pair;
        const float* wp = Wo + (half * 64) * CC + c;
        float acc2 = 0.f;
        #pragma unroll 8
        for (int cc2 = 0; cc2 < 64; cc2++)
            acc2 += sOF[half * 64 + cc2] * wp[cc2 * CC];
        sO[half][c] = acc2;
    }
    __syncthreads();
    if (tid < CC)
        out[(b * NN + i) * CC + tid] = bo[tid] + sO[0][tid] + sO[1][tid];
}

// ---------------- launch ----------------
extern "C" void kernel_launch(void* const* d_in, const int* in_sizes, int n_in,
                              void* d_out, int out_size)
{
    const float* feat    = (const float*)d_in[0];
    const float* centers = (const float*)d_in[1];
    const float* corners = (const float*)d_in[2];
    const float* lang    = (const float*)d_in[3];
    const float* Wq    = (const float*)d_in[4];
    const float* bq    = (const float*)d_in[5];
    const float* Wk    = (const float*)d_in[6];
    const float* bk    = (const float*)d_in[7];
    const float* Wv    = (const float*)d_in[8];
    const float* bv    = (const float*)d_in[9];
    const float* Wo    = (const float*)d_in[10];
    const float* bo    = (const float*)d_in[11];
    const float* Wrel  = (const float*)d_in[12];
    const float* brel  = (const float*)d_in[13];
    const float* Wtk   = (const float*)d_in[14];
    const float* btk   = (const float*)d_in[15];
    const float* Wtv   = (const float*)d_in[16];
    const float* btv   = (const float*)d_in[17];
    const float* Wbias = (const float*)d_in[18];
    const float* bbias = (const float*)d_in[19];

    k_combos<<<9, 256>>>(Wtk, btk, Wtv, btv, Wrel, brel, Wbias, bbias);
    k_lang<<<BB * TT, 128>>>(lang);
    k_qkv<<<BB * NN / 8, 128>>>(feat, corners, Wq, bq, Wk, bk, Wv, bv);
    k_main<<<dim3(NN, BB), 256>>>(centers, Wo, bo, (float*)d_out);
}

// round 2
// speedup vs baseline: 1.3880x; 1.3880x over previous
#include <cuda_runtime.h>
#include <math.h>

#define BB 8
#define NN 256
#define CC 128
#define TT 64
#define HH 4
#define GG 12
#define DD 32
#define FEPS 1e-6f

// ---------------- scratch (device globals; no allocation allowed) ----------------
__device__ float g_P[CC * GG];     // (Wtk @ Wrel^T)/sqrt(C)   [cc][g]
__device__ float g_p0[GG];         // (btk @ Wrel^T)/sqrt(C)
__device__ float g_pc[CC];         // (Wtk @ brel)/sqrt(C)
__device__ float g_pc0[1];         // (btk . brel)/sqrt(C)
__device__ float g_Qm[CC * HH];    // Wtv @ Wbias              [cc][h]
__device__ float g_q0[HH];         // btv @ Wbias
__device__ float g_Wrb[GG * HH];   // Wrel @ Wbias             [g][h]
__device__ float g_cb[HH];         // brel @ Wbias + bbias
__device__ float g_M[BB * GG * TT];   // per-batch score matrix [b][g][t]
__device__ float g_c0[BB * TT];       // per-batch score const  [b][t]
__device__ float g_Vb[BB * TT * HH];  // v_txt @ Wbias          [b][t][h]
__device__ float g_q[BB * HH * NN * DD];
__device__ float g_kT[BB * HH * DD * NN];   // TRANSPOSED: [b][h][d][j]
__device__ float g_v[BB * HH * NN * DD];
__device__ float g_sizes[BB * NN * 3];

// ---------------- kernel 0: tiny weight-combo precompute ----------------
__global__ void k_combos(const float* __restrict__ Wtk, const float* __restrict__ btk,
                         const float* __restrict__ Wtv, const float* __restrict__ btv,
                         const float* __restrict__ Wrel, const float* __restrict__ brel,
                         const float* __restrict__ Wbias, const float* __restrict__ bbias)
{
    const float isC = 0.08838834764831845f;  // 1/sqrt(128)
    int idx = blockIdx.x * blockDim.x + threadIdx.x;
    if (idx < 1536) {
        int cc = idx / 12, g = idx % 12;
        float s = 0.f;
        for (int c = 0; c < CC; c++) s += Wtk[cc * CC + c] * Wrel[g * CC + c];
        g_P[idx] = s * isC;
    } else if (idx < 1548) {
        int g = idx - 1536;
        float s = 0.f;
        for (int c = 0; c < CC; c++) s += btk[c] * Wrel[g * CC + c];
        g_p0[g] = s * isC;
    } else if (idx < 1676) {
        int cc = idx - 1548;
        float s = 0.f;
        for (int c = 0; c < CC; c++) s += Wtk[cc * CC + c] * brel[c];
        g_pc[cc] = s * isC;
    } else if (idx == 1676) {
        float s = 0.f;
        for (int c = 0; c < CC; c++) s += btk[c] * brel[c];
        g_pc0[0] = s * isC;
    } else if (idx < 2189) {
        int q = idx - 1677; int cc = q / 4, h = q % 4;
        float s = 0.f;
        for (int c = 0; c < CC; c++) s += Wtv[cc * CC + c] * Wbias[c * HH + h];
        g_Qm[cc * HH + h] = s;
    } else if (idx < 2193) {
        int h = idx - 2189;
        float s = 0.f;
        for (int c = 0; c < CC; c++) s += btv[c] * Wbias[c * HH + h];
        g_q0[h] = s;
    } else if (idx < 2241) {
        int q = idx - 2193; int g = q / 4, h = q % 4;
        float s = 0.f;
        for (int c = 0; c < CC; c++) s += Wrel[g * CC + c] * Wbias[c * HH + h];
        g_Wrb[q] = s;
    } else if (idx < 2245) {
        int h = idx - 2241;
        float s = 0.f;
        for (int c = 0; c < CC; c++) s += brel[c] * Wbias[c * HH + h];
        g_cb[h] = s + bbias[h];
    }
}

// ---------------- kernel 1: project lang tokens -> M, c0, Vb ----------------
__global__ __launch_bounds__(128) void k_lang(const float* __restrict__ lang)
{
    const int bt = blockIdx.x;            // 0 .. B*T-1
    const int b = bt >> 6, t = bt & 63;
    const int tid = threadIdx.x;
    __shared__ float L[CC];
    L[tid] = lang[bt * CC + tid];
    __syncthreads();
    const int wid = tid >> 5, lane = tid & 31;
    for (int o = wid; o < 17; o += 4) {
        float s = 0.f;
        if (o < 12) {
            for (int c = lane; c < CC; c += 32) s += L[c] * g_P[c * GG + o];
        } else if (o == 12) {
            for (int c = lane; c < CC; c += 32) s += L[c] * g_pc[c];
        } else {
            int h = o - 13;
            for (int c = lane; c < CC; c += 32) s += L[c] * g_Qm[c * HH + h];
        }
        #pragma unroll
        for (int off = 16; off; off >>= 1) s += __shfl_xor_sync(0xffffffffu, s, off);
        if (lane == 0) {
            if (o < 12)       g_M[(b * GG + o) * TT + t] = s + g_p0[o];
            else if (o == 12) g_c0[b * TT + t] = s + g_pc0[0];
            else              g_Vb[(b * TT + t) * HH + (o - 13)] = s + g_q0[o - 13];
        }
    }
}

// ---------------- kernel 2: QKV projections + box sizes ----------------
__global__ __launch_bounds__(128) void k_qkv(
    const float* __restrict__ feat, const float* __restrict__ corners,
    const float* __restrict__ Wq, const float* __restrict__ bq,
    const float* __restrict__ Wk, const float* __restrict__ bk,
    const float* __restrict__ Wv, const float* __restrict__ bv)
{
    const int blk = blockIdx.x;           // 256 blocks x 8 rows
    const int tid = threadIdx.x;          // 128 = output channel
    const int row0 = blk * 8;
    __shared__ float F[8][CC];
    #pragma unroll
    for (int r = 0; r < 8; r++) F[r][tid] = feat[(row0 + r) * CC + tid];
    __syncthreads();
    float aq[8], ak[8], av[8];
    #pragma unroll
    for (int r = 0; r < 8; r++) { aq[r] = bq[tid]; ak[r] = bk[tid]; av[r] = bv[tid]; }
    for (int cc = 0; cc < CC; cc++) {
        float wq = Wq[cc * CC + tid], wk = Wk[cc * CC + tid], wv = Wv[cc * CC + tid];
        #pragma unroll
        for (int r = 0; r < 8; r++) {
            float f = F[r][cc];
            aq[r] += f * wq; ak[r] += f * wk; av[r] += f * wv;
        }
    }
    const int h = tid >> 5, d = tid & 31;
    #pragma unroll
    for (int r = 0; r < 8; r++) {
        int bi = row0 + r; int b = bi >> 8, i = bi & 255;
        int o = ((b * HH + h) * NN + i) * DD + d;
        g_q[o] = aq[r]; g_v[o] = av[r];
        g_kT[((b * HH + h) * DD + d) * NN + i] = ak[r];   // transposed store
    }
    if (tid < 24) {
        int r = tid / 3, kd = tid % 3;
        int bi = row0 + r;
        float mx = -1e30f, mn = 1e30f;
        for (int cn = 0; cn < 8; cn++) {
            float v2 = corners[(bi * 8 + cn) * 3 + kd];
            mx = fmaxf(mx, v2); mn = fminf(mn, v2);
        }
        g_sizes[bi * 3 + kd] = mx - mn;
    }
}

// ---------------- kernel 3: fused geometry + lang-attn bias + attention + out proj ----------------
__global__ __launch_bounds__(256, 3) void k_main(
    const float* __restrict__ centers,
    const float* __restrict__ Wo,
    const float* __restrict__ bo,
    float* __restrict__ out)
{
    const int i = blockIdx.x;
    const int b = blockIdx.y;
    const int tid = threadIdx.x;

    __shared__ float4 sM4[GG * 16];   // [g][t/4]
    __shared__ float  sC0[TT];
    __shared__ float4 sVb4[TT];       // [t] -> h0..h3
    __shared__ float  sWrb[GG * HH];
    __shared__ float  sCb[HH];
    __shared__ float  sQ[CC];         // q row for i, [h][d]
    __shared__ float  sCi[3], sSi[3];
    __shared__ float4 sE4[NN];        // exp(logit - max) per j, 4 heads
    __shared__ float  sRedM[8 * HH];
    __shared__ float  sRedS[8 * HH];
    __shared__ float4 sAV[8][32];     // partial AV per jgroup: [wg][h*8+d4]
    __shared__ float  sOF[CC];
    __shared__ float  sOP[2][CC];

    float* sM = (float*)sM4;
    float* sVb = (float*)sVb4;
    float* sE = (float*)sE4;

    {
        const float* Mb = g_M + b * (GG * TT);
        for (int x = tid; x < GG * TT; x += 256) sM[x] = Mb[x];
        if (tid < TT) sC0[tid] = g_c0[b * TT + tid];
        sVb[tid] = g_Vb[b * TT * HH + tid];       // 256 elements
        if (tid < GG * HH) sWrb[tid] = g_Wrb[tid];
        if (tid < HH) sCb[tid] = g_cb[tid];
        if (tid < CC)
            sQ[tid] = g_q[((b * HH + (tid >> 5)) * NN + i) * DD + (tid & 31)];
        if (tid < 3) {
            sCi[tid] = centers[(b * NN + i) * 3 + tid];
            sSi[tid] = g_sizes[(b * NN + i) * 3 + tid];
        }
    }
    __syncthreads();

    const int j = tid;
    float cjx = centers[(b * NN + j) * 3 + 0];
    float cjy = centers[(b * NN + j) * 3 + 1];
    float cjz = centers[(b * NN + j) * 3 + 2];
    float rx = cjx - sCi[0], ry = cjy - sCi[1], rz = cjz - sCi[2];
    float r2all = rx * rx + ry * ry + rz * rz;
    float r2h   = rx * rx + ry * ry;
    float dist  = r2all * rsqrtf(r2all + 1e-30f);
    float horiz = r2h * rsqrtf(r2h + 1e-30f);
    float dl = __logf(dist + FEPS);
    float ce = __fdividef(rz, dist + FEPS);
    float sj0 = g_sizes[(b * NN + j) * 3 + 0];
    float sj1 = g_sizes[(b * NN + j) * 3 + 1];
    float sj2 = g_sizes[(b * NN + j) * 3 + 2];
    float geom[GG];
    geom[0] = rx; geom[1] = ry; geom[2] = rz;
    geom[3] = dl; geom[4] = horiz; geom[5] = ce;
    geom[6] = sj0 - sSi[0]; geom[7] = sj1 - sSi[1]; geom[8] = sj2 - sSi[2];
    geom[9]  = __fdividef(sj0, sSi[0] + FEPS);
    geom[10] = __fdividef(sj1, sSi[1] + FEPS);
    geom[11] = __fdividef(sj2, sSi[2] + FEPS);

    // ---- token scores + online softmax over 2 chunks of 32 tokens ----
    float m = -1e30f, ssum = 0.f;
    float a0 = 0.f, a1 = 0.f, a2 = 0.f, a3 = 0.f;
    #pragma unroll
    for (int ch = 0; ch < 2; ch++) {
        float sc[32];
        #pragma unroll
        for (int t = 0; t < 32; t++) sc[t] = sC0[ch * 32 + t];
        #pragma unroll
        for (int g = 0; g < GG; g++) {
            float gv = geom[g];
            #pragma unroll
            for (int t4 = 0; t4 < 8; t4++) {
                float4 mm = sM4[g * 16 + ch * 8 + t4];
                sc[t4 * 4 + 0] += gv * mm.x;
                sc[t4 * 4 + 1] += gv * mm.y;
                sc[t4 * 4 + 2] += gv * mm.z;
                sc[t4 * 4 + 3] += gv * mm.w;
            }
        }
        float cm = sc[0];
        #pragma unroll
        for (int t = 1; t < 32; t++) cm = fmaxf(cm, sc[t]);
        float newm = fmaxf(m, cm);
        float scale = __expf(m - newm);
        ssum *= scale; a0 *= scale; a1 *= scale; a2 *= scale; a3 *= scale;
        #pragma unroll
        for (int t = 0; t < 32; t++) {
            float e = __expf(sc[t] - newm);
            ssum += e;
            float4 vb = sVb4[ch * 32 + t];
            a0 += e * vb.x; a1 += e * vb.y; a2 += e * vb.z; a3 += e * vb.w;
        }
        m = newm;
    }
    float inv = __fdividef(1.f, ssum);

    // bias per head: geom@Wrb + cb + (alpha @ Vb)
    float bh0 = sCb[0], bh1 = sCb[1], bh2 = sCb[2], bh3 = sCb[3];
    #pragma unroll
    for (int g = 0; g < GG; g++) {
        float gv = geom[g];
        bh0 += gv * sWrb[g * 4 + 0];
        bh1 += gv * sWrb[g * 4 + 1];
        bh2 += gv * sWrb[g * 4 + 2];
        bh3 += gv * sWrb[g * 4 + 3];
    }
    float bhv[HH];
    bhv[0] = bh0 + a0 * inv; bhv[1] = bh1 + a1 * inv;
    bhv[2] = bh2 + a2 * inv; bhv[3] = bh3 + a3 * inv;

    // ---- QK logits (coalesced via transposed K) ----
    float lg[HH];
    {
        const float* kT = g_kT + (size_t)(b * HH) * DD * NN + j;
        #pragma unroll
        for (int h = 0; h < HH; h++) {
            float dot = 0.f;
            #pragma unroll 8
            for (int d = 0; d < DD; d++)
                dot += sQ[h * DD + d] * kT[(h * DD + d) * NN];
            lg[h] = dot * 0.17677669529663687f + bhv[h];   // 1/sqrt(32)
        }
    }

    // ---- block softmax over j (256) per head ----
    const int wid = tid >> 5, lane = tid & 31;
    float m4[HH];
    #pragma unroll
    for (int h = 0; h < HH; h++) m4[h] = lg[h];
    #pragma unroll
    for (int off = 16; off; off >>= 1) {
        #pragma unroll
        for (int h = 0; h < HH; h++)
            m4[h] = fmaxf(m4[h], __shfl_xor_sync(0xffffffffu, m4[h], off));
    }
    if (lane == 0) {
        #pragma unroll
        for (int h = 0; h < HH; h++) sRedM[wid * 4 + h] = m4[h];
    }
    __syncthreads();
    float hmax[HH];
    #pragma unroll
    for (int h = 0; h < HH; h++) {
        float mm = sRedM[h];
        #pragma unroll
        for (int w = 1; w < 8; w++) mm = fmaxf(mm, sRedM[w * 4 + h]);
        hmax[h] = mm;
    }
    float e4[HH], s4[HH];
    #pragma unroll
    for (int h = 0; h < HH; h++) { e4[h] = __expf(lg[h] - hmax[h]); s4[h] = e4[h]; }
    sE4[tid] = make_float4(e4[0], e4[1], e4[2], e4[3]);
    #pragma unroll
    for (int off = 16; off; off >>= 1) {
        #pragma unroll
        for (int h = 0; h < HH; h++)
            s4[h] += __shfl_xor_sync(0xffffffffu, s4[h], off);
    }
    __syncthreads();   // sRedM reads done; sE4 visible after next sync
    if (lane == 0) {
        #pragma unroll
        for (int h = 0; h < HH; h++) sRedS[wid * 4 + h] = s4[h];
    }
    __syncthreads();

    // ---- attention output: AV with float4 loads ----
    {
        const int h = lane >> 3, d4 = lane & 7;   // 4 heads x 8 float4-chunks
        const float4* v4 = (const float4*)g_v + (size_t)(b * HH + h) * NN * 8 + d4;
        float4 acc = make_float4(0.f, 0.f, 0.f, 0.f);
        #pragma unroll 8
        for (int jj = 0; jj < 32; jj++) {
            int j2 = wid * 32 + jj;
            float e = sE[j2 * 4 + h];
            float4 vv = v4[(size_t)j2 * 8];
            acc.x += e * vv.x; acc.y += e * vv.y;
            acc.z += e * vv.z; acc.w += e * vv.w;
        }
        sAV[wid][lane] = acc;
    }
    __syncthreads();
    if (tid < CC) {
        const int h = tid >> 5, d = tid & 31, d4 = d >> 2, cm2 = d & 3;
        float s = 0.f;
        #pragma unroll
        for (int w = 0; w < 8; w++) s += ((const float*)&sAV[w][h * 8 + d4])[cm2];
        float denom = sRedS[h];
        #pragma unroll
        for (int w = 1; w < 8; w++) denom += sRedS[w * 4 + h];
        sOF[tid] = __fdividef(s, denom);
    }
    __syncthreads();

    // ---- output projection: out[b,i,:] = sOF @ Wo + bo ----
    {
        const int c = tid & 127;
        const int half = tid >> 7;
        const float* wp = Wo + (half * 64) * CC + c;
        float acc2 = 0.f;
        #pragma unroll 8
        for (int cc2 = 0; cc2 < 64; cc2++)
            acc2 += sOF[half * 64 + cc2] * wp[cc2 * CC];
        sOP[half][c] = acc2;
    }
    __syncthreads();
    if (tid < CC)
        out[(b * NN + i) * CC + tid] = bo[tid] + sOP[0][tid] + sOP[1][tid];
}

// ---------------- launch ----------------
extern "C" void kernel_launch(void* const* d_in, const int* in_sizes, int n_in,
                              void* d_out, int out_size)
{
    const float* feat    = (const float*)d_in[0];
    const float* centers = (const float*)d_in[1];
    const float* corners = (const float*)d_in[2];
    const float* lang    = (const float*)d_in[3];
    const float* Wq    = (const float*)d_in[4];
    const float* bq    = (const float*)d_in[5];
    const float* Wk    = (const float*)d_in[6];
    const float* bk    = (const float*)d_in[7];
    const float* Wv    = (const float*)d_in[8];
    const float* bv    = (const float*)d_in[9];
    const float* Wo    = (const float*)d_in[10];
    const float* bo    = (const float*)d_in[11];
    const float* Wrel  = (const float*)d_in[12];
    const float* brel  = (const float*)d_in[13];
    const float* Wtk   = (const float*)d_in[14];
    const float* btk   = (const float*)d_in[15];
    const float* Wtv   = (const float*)d_in[16];
    const float* btv   = (const float*)d_in[17];
    const float* Wbias = (const float*)d_in[18];
    const float* bbias = (const float*)d_in[19];

    k_combos<<<9, 256>>>(Wtk, btk, Wtv, btv, Wrel, brel, Wbias, bbias);
    k_lang<<<BB * TT, 128>>>(lang);
    k_qkv<<<BB * NN / 8, 128>>>(feat, corners, Wq, bq, Wk, bk, Wv, bv);
    k_main<<<dim3(NN, BB), 256>>>(centers, Wo, bo, (float*)d_out);
}

// round 3
// speedup vs baseline: 1.4766x; 1.0638x over previous
#include <cuda_runtime.h>
#include <math.h>
#include <stdint.h>

#define BB 8
#define NN 256
#define CC 128
#define TT 64
#define HH 4
#define GG 12
#define DD 32
#define FEPS 1e-6f

typedef unsigned long long ull;

// ---- f32x2 packed-math helpers (sm_103a FMA2 path, PTX-only) ----
__device__ __forceinline__ ull pack2(float lo, float hi) {
    ull d;
    asm("mov.b64 %0, {%1, %2};" : "=l"(d)
        : "r"(__float_as_uint(lo)), "r"(__float_as_uint(hi)));
    return d;
}
__device__ __forceinline__ float2 unpack2(ull s) {
    uint32_t a, b;
    asm("mov.b64 {%0, %1}, %2;" : "=r"(a), "=r"(b) : "l"(s));
    return make_float2(__uint_as_float(a), __uint_as_float(b));
}
__device__ __forceinline__ ull fma2(ull a, ull b, ull c) {
    ull d;
    asm("fma.rn.f32x2 %0, %1, %2, %3;" : "=l"(d) : "l"(a), "l"(b), "l"(c));
    return d;
}
__device__ __forceinline__ ull mul2(ull a, ull b) {
    ull d;
    asm("mul.rn.f32x2 %0, %1, %2;" : "=l"(d) : "l"(a), "l"(b));
    return d;
}
#define LDS2(a, b, addr) \
    asm volatile("ld.shared.v2.u64 {%0, %1}, [%2];" : "=l"(a), "=l"(b) : "r"(addr))
#define LDG2(a, b, p) \
    asm volatile("ld.global.nc.v2.u64 {%0, %1}, [%2];" : "=l"(a), "=l"(b) : "l"(p))

// ---------------- scratch (device globals; no allocation allowed) ----------------
__device__ float g_P[CC * GG];
__device__ float g_p0[GG];
__device__ float g_pc[CC];
__device__ float g_pc0[1];
__device__ float g_Qm[CC * HH];
__device__ float g_q0[HH];
__device__ float g_Wrb[GG * HH];
__device__ float g_cb[HH];
__device__ float g_M[BB * GG * TT];   // [b][g][t]
__device__ float g_c0[BB * TT];
__device__ float g_Vb[BB * TT * HH];
__device__ float g_q[BB * HH * NN * DD];
__device__ float g_kT[BB * HH * DD * NN];   // [b][h][d][j]
__device__ float g_v[BB * HH * NN * DD];
__device__ float g_sizes[BB * NN * 3];

// ---------------- kernel 0: tiny weight-combo precompute ----------------
__global__ void k_combos(const float* __restrict__ Wtk, const float* __restrict__ btk,
                         const float* __restrict__ Wtv, const float* __restrict__ btv,
                         const float* __restrict__ Wrel, const float* __restrict__ brel,
                         const float* __restrict__ Wbias, const float* __restrict__ bbias)
{
    const float isC = 0.08838834764831845f;  // 1/sqrt(128)
    int idx = blockIdx.x * blockDim.x + threadIdx.x;
    if (idx < 1536) {
        int cc = idx / 12, g = idx % 12;
        float s = 0.f;
        for (int c = 0; c < CC; c++) s += Wtk[cc * CC + c] * Wrel[g * CC + c];
        g_P[idx] = s * isC;
    } else if (idx < 1548) {
        int g = idx - 1536;
        float s = 0.f;
        for (int c = 0; c < CC; c++) s += btk[c] * Wrel[g * CC + c];
        g_p0[g] = s * isC;
    } else if (idx < 1676) {
        int cc = idx - 1548;
        float s = 0.f;
        for (int c = 0; c < CC; c++) s += Wtk[cc * CC + c] * brel[c];
        g_pc[cc] = s * isC;
    } else if (idx == 1676) {
        float s = 0.f;
        for (int c = 0; c < CC; c++) s += btk[c] * brel[c];
        g_pc0[0] = s * isC;
    } else if (idx < 2189) {
        int q = idx - 1677; int cc = q / 4, h = q % 4;
        float s = 0.f;
        for (int c = 0; c < CC; c++) s += Wtv[cc * CC + c] * Wbias[c * HH + h];
        g_Qm[cc * HH + h] = s;
    } else if (idx < 2193) {
        int h = idx - 2189;
        float s = 0.f;
        for (int c = 0; c < CC; c++) s += btv[c] * Wbias[c * HH + h];
        g_q0[h] = s;
    } else if (idx < 2241) {
        int q = idx - 2193; int g = q / 4, h = q % 4;
        float s = 0.f;
        for (int c = 0; c < CC; c++) s += Wrel[g * CC + c] * Wbias[c * HH + h];
        g_Wrb[q] = s;
    } else if (idx < 2245) {
        int h = idx - 2241;
        float s = 0.f;
        for (int c = 0; c < CC; c++) s += brel[c] * Wbias[c * HH + h];
        g_cb[h] = s + bbias[h];
    }
}

// ---------------- kernel 1: project lang tokens -> M, c0, Vb ----------------
__global__ __launch_bounds__(128) void k_lang(const float* __restrict__ lang)
{
    const int bt = blockIdx.x;
    const int b = bt >> 6, t = bt & 63;
    const int tid = threadIdx.x;
    __shared__ float L[CC];
    L[tid] = lang[bt * CC + tid];
    __syncthreads();
    const int wid = tid >> 5, lane = tid & 31;
    for (int o = wid; o < 17; o += 4) {
        float s = 0.f;
        if (o < 12) {
            for (int c = lane; c < CC; c += 32) s += L[c] * g_P[c * GG + o];
        } else if (o == 12) {
            for (int c = lane; c < CC; c += 32) s += L[c] * g_pc[c];
        } else {
            int h = o - 13;
            for (int c = lane; c < CC; c += 32) s += L[c] * g_Qm[c * HH + h];
        }
        #pragma unroll
        for (int off = 16; off; off >>= 1) s += __shfl_xor_sync(0xffffffffu, s, off);
        if (lane == 0) {
            if (o < 12)       g_M[(b * GG + o) * TT + t] = s + g_p0[o];
            else if (o == 12) g_c0[b * TT + t] = s + g_pc0[0];
            else              g_Vb[(b * TT + t) * HH + (o - 13)] = s + g_q0[o - 13];
        }
    }
}

// ---------------- kernel 2: QKV projections + box sizes ----------------
__global__ __launch_bounds__(128) void k_qkv(
    const float* __restrict__ feat, const float* __restrict__ corners,
    const float* __restrict__ Wq, const float* __restrict__ bq,
    const float* __restrict__ Wk, const float* __restrict__ bk,
    const float* __restrict__ Wv, const float* __restrict__ bv)
{
    const int blk = blockIdx.x;
    const int tid = threadIdx.x;
    const int row0 = blk * 8;
    __shared__ float F[8][CC];
    #pragma unroll
    for (int r = 0; r < 8; r++) F[r][tid] = feat[(row0 + r) * CC + tid];
    __syncthreads();
    float aq[8], ak[8], av[8];
    #pragma unroll
    for (int r = 0; r < 8; r++) { aq[r] = bq[tid]; ak[r] = bk[tid]; av[r] = bv[tid]; }
    for (int cc = 0; cc < CC; cc++) {
        float wq = Wq[cc * CC + tid], wk = Wk[cc * CC + tid], wv = Wv[cc * CC + tid];
        #pragma unroll
        for (int r = 0; r < 8; r++) {
            float f = F[r][cc];
            aq[r] += f * wq; ak[r] += f * wk; av[r] += f * wv;
        }
    }
    const int h = tid >> 5, d = tid & 31;
    #pragma unroll
    for (int r = 0; r < 8; r++) {
        int bi = row0 + r; int b = bi >> 8, i = bi & 255;
        int o = ((b * HH + h) * NN + i) * DD + d;
        g_q[o] = aq[r]; g_v[o] = av[r];
        g_kT[((b * HH + h) * DD + d) * NN + i] = ak[r];
    }
    if (tid < 24) {
        int r = tid / 3, kd = tid % 3;
        int bi = row0 + r;
        float mx = -1e30f, mn = 1e30f;
        for (int cn = 0; cn < 8; cn++) {
            float v2 = corners[(bi * 8 + cn) * 3 + kd];
            mx = fmaxf(mx, v2); mn = fminf(mn, v2);
        }
        g_sizes[bi * 3 + kd] = mx - mn;
    }
}

// ---------------- kernel 3: fused main ----------------
__global__ __launch_bounds__(256, 3) void k_main(
    const float* __restrict__ centers,
    const float* __restrict__ Wo,
    const float* __restrict__ bo,
    float* __restrict__ out)
{
    const int i = blockIdx.x;
    const int b = blockIdx.y;
    const int tid = threadIdx.x;

    __shared__ float4 sCoef4[9 * 16];  // 9 merged coefficient rows x 64 tokens
    __shared__ float4 sC0b4[16];       // adjusted per-block constant
    __shared__ float4 sVb4[TT];        // [t] -> h0..h3
    __shared__ float  sWrb[GG * HH];
    __shared__ float  sCb[HH];
    __shared__ float  sQ[CC];
    __shared__ float  sCi[3], sSi[3];
    __shared__ float4 sE4[NN];
    __shared__ float  sRedM[8 * HH];
    __shared__ float  sRedS[8 * HH];
    __shared__ float  sAVf[8][CC];
    __shared__ float  sOF[CC];
    __shared__ float  sOP[2][CC];

    float* sCoef = (float*)sCoef4;
    float* sC0b  = (float*)sC0b4;
    float* sVb   = (float*)sVb4;
    float* sE    = (float*)sE4;

    const float* Mb = g_M + b * (GG * TT);

    // ---- phase A: loads ----
    for (int x = tid; x < 6 * TT; x += 256) sCoef[x] = Mb[x];   // raw rows 0..5
    sVb[tid] = g_Vb[b * TT * HH + tid];
    if (tid < GG * HH) sWrb[tid] = g_Wrb[tid];
    if (tid < HH) sCb[tid] = g_cb[tid];
    if (tid < CC)
        sQ[tid] = g_q[((b * HH + (tid >> 5)) * NN + i) * DD + (tid & 31)];
    if (tid < 3) {
        sCi[tid] = centers[(b * NN + i) * 3 + tid];
        sSi[tid] = g_sizes[(b * NN + i) * 3 + tid];
    }
    __syncthreads();

    // ---- phase B: per-block coefficient folding (i-side absorbed) ----
    if (tid < TT) {
        const int t = tid;
        float inv0 = __fdividef(1.f, sSi[0] + FEPS);
        float inv1 = __fdividef(1.f, sSi[1] + FEPS);
        float inv2 = __fdividef(1.f, sSi[2] + FEPS);
        float m6 = Mb[6 * TT + t],  m7 = Mb[7 * TT + t],  m8 = Mb[8 * TT + t];
        float m9 = Mb[9 * TT + t], m10 = Mb[10 * TT + t], m11 = Mb[11 * TT + t];
        float c0 = g_c0[b * TT + t]
                 - sCi[0] * sCoef[0 * TT + t]
                 - sCi[1] * sCoef[1 * TT + t]
                 - sCi[2] * sCoef[2 * TT + t]
                 - sSi[0] * m6 - sSi[1] * m7 - sSi[2] * m8;
        sC0b[t] = c0;
        sCoef[6 * TT + t] = m6 + inv0 * m9;
        sCoef[7 * TT + t] = m7 + inv1 * m10;
        sCoef[8 * TT + t] = m8 + inv2 * m11;
    }
    __syncthreads();

    // ---- per-thread geometry (j = tid) ----
    const int j = tid;
    float cjx = centers[(b * NN + j) * 3 + 0];
    float cjy = centers[(b * NN + j) * 3 + 1];
    float cjz = centers[(b * NN + j) * 3 + 2];
    float rx = cjx - sCi[0], ry = cjy - sCi[1], rz = cjz - sCi[2];
    float r2all = rx * rx + ry * ry + rz * rz;
    float r2h   = rx * rx + ry * ry;
    float dist  = r2all * rsqrtf(r2all + 1e-30f);
    float horiz = r2h * rsqrtf(r2h + 1e-30f);
    float dl = __logf(dist + FEPS);
    float ce = __fdividef(rz, dist + FEPS);
    float sj0 = g_sizes[(b * NN + j) * 3 + 0];
    float sj1 = g_sizes[(b * NN + j) * 3 + 1];
    float sj2 = g_sizes[(b * NN + j) * 3 + 2];

    // full geometry (for the 12x4 bias matvec)
    float geom[GG];
    geom[0] = rx; geom[1] = ry; geom[2] = rz;
    geom[3] = dl; geom[4] = horiz; geom[5] = ce;
    geom[6] = sj0 - sSi[0]; geom[7] = sj1 - sSi[1]; geom[8] = sj2 - sSi[2];
    geom[9]  = sj0 * __fdividef(1.f, sSi[0] + FEPS);
    geom[10] = sj1 * __fdividef(1.f, sSi[1] + FEPS);
    geom[11] = sj2 * __fdividef(1.f, sSi[2] + FEPS);

    // 9 merged coefficients (j-side values), packed for f32x2
    ull cv2[9];
    cv2[0] = pack2(cjx, cjx); cv2[1] = pack2(cjy, cjy); cv2[2] = pack2(cjz, cjz);
    cv2[3] = pack2(dl, dl);   cv2[4] = pack2(horiz, horiz); cv2[5] = pack2(ce, ce);
    cv2[6] = pack2(sj0, sj0); cv2[7] = pack2(sj1, sj1); cv2[8] = pack2(sj2, sj2);

    const uint32_t c0Addr   = (uint32_t)__cvta_generic_to_shared(sC0b4);
    const uint32_t coefAddr = (uint32_t)__cvta_generic_to_shared(sCoef4);
    const uint32_t vbAddr   = (uint32_t)__cvta_generic_to_shared(sVb4);

    // ---- token scores + online softmax (2 chunks of 32 tokens), packed f32x2 ----
    float m = -1e30f, ssum = 0.f;
    ull aA = 0ull, aB = 0ull;   // packed accumulators: (h0,h1), (h2,h3)
    #pragma unroll
    for (int ch = 0; ch < 2; ch++) {
        ull sc2[16];
        #pragma unroll
        for (int t4 = 0; t4 < 8; t4++)
            LDS2(sc2[2 * t4], sc2[2 * t4 + 1], c0Addr + (ch * 8 + t4) * 16);
        #pragma unroll
        for (int g = 0; g < 9; g++) {
            #pragma unroll
            for (int t4 = 0; t4 < 8; t4++) {
                ull mA, mB;
                LDS2(mA, mB, coefAddr + (g * 16 + ch * 8 + t4) * 16);
                sc2[2 * t4]     = fma2(cv2[g], mA, sc2[2 * t4]);
                sc2[2 * t4 + 1] = fma2(cv2[g], mB, sc2[2 * t4 + 1]);
            }
        }
        float cm = -1e30f;
        #pragma unroll
        for (int k = 0; k < 16; k++) {
            float2 v = unpack2(sc2[k]);
            cm = fmaxf(cm, fmaxf(v.x, v.y));
        }
        float newm = fmaxf(m, cm);
        float scale = __expf(m - newm);
        ssum *= scale;
        ull s2 = pack2(scale, scale);
        aA = mul2(aA, s2); aB = mul2(aB, s2);
        #pragma unroll
        for (int k = 0; k < 16; k++) {
            float2 v = unpack2(sc2[k]);
            float e0 = __expf(v.x - newm);
            float e1 = __expf(v.y - newm);
            ssum += e0 + e1;
            ull vA, vB;
            LDS2(vA, vB, vbAddr + (ch * 32 + 2 * k) * 16);
            ull e02 = pack2(e0, e0);
            aA = fma2(e02, vA, aA); aB = fma2(e02, vB, aB);
            LDS2(vA, vB, vbAddr + (ch * 32 + 2 * k + 1) * 16);
            ull e12 = pack2(e1, e1);
            aA = fma2(e12, vA, aA); aB = fma2(e12, vB, aB);
        }
        m = newm;
    }
    float inv = __fdividef(1.f, ssum);
    float2 a01 = unpack2(aA), a23 = unpack2(aB);

    // ---- bias per head: geom@Wrb + cb + alpha@Vb ----
    float bh0 = sCb[0], bh1 = sCb[1], bh2 = sCb[2], bh3 = sCb[3];
    #pragma unroll
    for (int g = 0; g < GG; g++) {
        float gv = geom[g];
        bh0 += gv * sWrb[g * 4 + 0];
        bh1 += gv * sWrb[g * 4 + 1];
        bh2 += gv * sWrb[g * 4 + 2];
        bh3 += gv * sWrb[g * 4 + 3];
    }
    float bhv[HH];
    bhv[0] = bh0 + a01.x * inv; bhv[1] = bh1 + a01.y * inv;
    bhv[2] = bh2 + a23.x * inv; bhv[3] = bh3 + a23.y * inv;

    // ---- QK logits (coalesced via transposed K) ----
    float lg[HH];
    {
        const float* kT = g_kT + (size_t)(b * HH) * DD * NN + j;
        #pragma unroll
        for (int h = 0; h < HH; h++) {
            float dot = 0.f;
            #pragma unroll 8
            for (int d = 0; d < DD; d++)
                dot += sQ[h * DD + d] * kT[(h * DD + d) * NN];
            lg[h] = dot * 0.17677669529663687f + bhv[h];   // 1/sqrt(32)
        }
    }

    // ---- block softmax over j (256) per head ----
    const int wid = tid >> 5, lane = tid & 31;
    float m4[HH];
    #pragma unroll
    for (int h = 0; h < HH; h++) m4[h] = lg[h];
    #pragma unroll
    for (int off = 16; off; off >>= 1) {
        #pragma unroll
        for (int h = 0; h < HH; h++)
            m4[h] = fmaxf(m4[h], __shfl_xor_sync(0xffffffffu, m4[h], off));
    }
    if (lane == 0) {
        #pragma unroll
        for (int h = 0; h < HH; h++) sRedM[wid * 4 + h] = m4[h];
    }
    __syncthreads();
    float hmax[HH];
    #pragma unroll
    for (int h = 0; h < HH; h++) {
        float mm = sRedM[h];
        #pragma unroll
        for (int w = 1; w < 8; w++) mm = fmaxf(mm, sRedM[w * 4 + h]);
        hmax[h] = mm;
    }
    float e4[HH], s4[HH];
    #pragma unroll
    for (int h = 0; h < HH; h++) { e4[h] = __expf(lg[h] - hmax[h]); s4[h] = e4[h]; }
    sE4[tid] = make_float4(e4[0], e4[1], e4[2], e4[3]);
    #pragma unroll
    for (int off = 16; off; off >>= 1) {
        #pragma unroll
        for (int h = 0; h < HH; h++)
            s4[h] += __shfl_xor_sync(0xffffffffu, s4[h], off);
    }
    __syncthreads();
    if (lane == 0) {
        #pragma unroll
        for (int h = 0; h < HH; h++) sRedS[wid * 4 + h] = s4[h];
    }
    __syncthreads();

    // ---- attention output: AV with packed fma ----
    {
        const int h = lane >> 3, d4 = lane & 7;   // 4 heads x 8 float4-chunks
        const float* vp = g_v + (size_t)(b * HH + h) * NN * DD + d4 * 4;
        ull accA = 0ull, accB = 0ull;
        #pragma unroll 8
        for (int jj = 0; jj < 32; jj++) {
            int j2 = wid * 32 + jj;
            float e = sE[j2 * 4 + h];
            ull vA, vB;
            LDG2(vA, vB, vp + (size_t)j2 * DD);
            ull e2 = pack2(e, e);
            accA = fma2(e2, vA, accA);
            accB = fma2(e2, vB, accB);
        }
        ull* dst = (ull*)&sAVf[wid][lane * 4];
        dst[0] = accA; dst[1] = accB;
    }
    __syncthreads();
    if (tid < CC) {
        const int h = tid >> 5, d = tid & 31;
        float s = 0.f;
        #pragma unroll
        for (int w = 0; w < 8; w++) s += sAVf[w][h * 32 + d];
        float denom = sRedS[h];
        #pragma unroll
        for (int w = 1; w < 8; w++) denom += sRedS[w * 4 + h];
        sOF[tid] = __fdividef(s, denom);
    }
    __syncthreads();

    // ---- output projection ----
    {
        const int c = tid & 127;
        const int half = tid >> 7;
        const float* wp = Wo + (half * 64) * CC + c;
        float acc2 = 0.f;
        #pragma unroll 8
        for (int cc2 = 0; cc2 < 64; cc2++)
            acc2 += sOF[half * 64 + cc2] * wp[cc2 * CC];
        sOP[half][c] = acc2;
    }
    __syncthreads();
    if (tid < CC)
        out[(b * NN + i) * CC + tid] = bo[tid] + sOP[0][tid] + sOP[1][tid];
}

// ---------------- launch ----------------
extern "C" void kernel_launch(void* const* d_in, const int* in_sizes, int n_in,
                              void* d_out, int out_size)
{
    const float* feat    = (const float*)d_in[0];
    const float* centers = (const float*)d_in[1];
    const float* corners = (const float*)d_in[2];
    const float* lang    = (const float*)d_in[3];
    const float* Wq    = (const float*)d_in[4];
    const float* bq    = (const float*)d_in[5];
    const float* Wk    = (const float*)d_in[6];
    const float* bk    = (const float*)d_in[7];
    const float* Wv    = (const float*)d_in[8];
    const float* bv    = (const float*)d_in[9];
    const float* Wo    = (const float*)d_in[10];
    const float* bo    = (const float*)d_in[11];
    const float* Wrel  = (const float*)d_in[12];
    const float* brel  = (const float*)d_in[13];
    const float* Wtk   = (const float*)d_in[14];
    const float* btk   = (const float*)d_in[15];
    const float* Wtv   = (const float*)d_in[16];
    const float* btv   = (const float*)d_in[17];
    const float* Wbias = (const float*)d_in[18];
    const float* bbias = (const float*)d_in[19];

    k_combos<<<9, 256>>>(Wtk, btk, Wtv, btv, Wrel, brel, Wbias, bbias);
    k_lang<<<BB * TT, 128>>>(lang);
    k_qkv<<<BB * NN / 8, 128>>>(feat, corners, Wq, bq, Wk, bk, Wv, bv);
    k_main<<<dim3(NN, BB), 256>>>(centers, Wo, bo, (float*)d_out);
}

// round 4
// speedup vs baseline: 1.6285x; 1.1029x over previous
#include <cuda_runtime.h>
#include <math.h>
#include <stdint.h>

#define BB 8
#define NN 256
#define CC 128
#define TT 64
#define HH 4
#define GG 12
#define DD 32
#define FEPS 1e-6f

typedef unsigned long long ull;

// ---- f32x2 packed-math helpers ----
__device__ __forceinline__ ull pack2(float lo, float hi) {
    ull d;
    asm("mov.b64 %0, {%1, %2};" : "=l"(d)
        : "r"(__float_as_uint(lo)), "r"(__float_as_uint(hi)));
    return d;
}
__device__ __forceinline__ float2 unpack2(ull s) {
    uint32_t a, b;
    asm("mov.b64 {%0, %1}, %2;" : "=r"(a), "=r"(b) : "l"(s));
    return make_float2(__uint_as_float(a), __uint_as_float(b));
}
__device__ __forceinline__ ull fma2(ull a, ull b, ull c) {
    ull d;
    asm("fma.rn.f32x2 %0, %1, %2, %3;" : "=l"(d) : "l"(a), "l"(b), "l"(c));
    return d;
}
__device__ __forceinline__ ull mul2(ull a, ull b) {
    ull d;
    asm("mul.rn.f32x2 %0, %1, %2;" : "=l"(d) : "l"(a), "l"(b));
    return d;
}
#define LDS2(a, b, addr) \
    asm volatile("ld.shared.v2.u64 {%0, %1}, [%2];" : "=l"(a), "=l"(b) : "r"(addr))
#define LDG2(a, b, p) \
    asm volatile("ld.global.nc.v2.u64 {%0, %1}, [%2];" : "=l"(a), "=l"(b) : "l"(p))

// ---------------- scratch ----------------
__device__ float g_P[CC * GG];
__device__ float g_p0[GG];
__device__ float g_pc[CC];
__device__ float g_pc0[1];
__device__ float g_Qm[CC * HH];
__device__ float g_q0[HH];
__device__ float g_Wrb[GG * HH];
__device__ float g_cb[HH];
__device__ float g_M[BB * GG * TT];
__device__ float g_c0[BB * TT];
__device__ float g_Vb[BB * TT * HH];
__device__ float g_q[BB * HH * NN * DD];
__device__ float g_kT[BB * HH * DD * NN];      // [b][h][d][j]
__device__ float g_v[BB * HH * NN * DD];
__device__ float g_sizes[BB * NN * 3];
__device__ float g_logits[BB * HH * NN * NN];  // [b][h][i][j] (scaled QK)

// ---------------- kernel 0: weight combos ----------------
__global__ void k_combos(const float* __restrict__ Wtk, const float* __restrict__ btk,
                         const float* __restrict__ Wtv, const float* __restrict__ btv,
                         const float* __restrict__ Wrel, const float* __restrict__ brel,
                         const float* __restrict__ Wbias, const float* __restrict__ bbias)
{
    const float isC = 0.08838834764831845f;  // 1/sqrt(128)
    int idx = blockIdx.x * blockDim.x + threadIdx.x;
    if (idx < 1536) {
        int cc = idx / 12, g = idx % 12;
        float s = 0.f;
        for (int c = 0; c < CC; c++) s += Wtk[cc * CC + c] * Wrel[g * CC + c];
        g_P[idx] = s * isC;
    } else if (idx < 1548) {
        int g = idx - 1536;
        float s = 0.f;
        for (int c = 0; c < CC; c++) s += btk[c] * Wrel[g * CC + c];
        g_p0[g] = s * isC;
    } else if (idx < 1676) {
        int cc = idx - 1548;
        float s = 0.f;
        for (int c = 0; c < CC; c++) s += Wtk[cc * CC + c] * brel[c];
        g_pc[cc] = s * isC;
    } else if (idx == 1676) {
        float s = 0.f;
        for (int c = 0; c < CC; c++) s += btk[c] * brel[c];
        g_pc0[0] = s * isC;
    } else if (idx < 2189) {
        int q = idx - 1677; int cc = q / 4, h = q % 4;
        float s = 0.f;
        for (int c = 0; c < CC; c++) s += Wtv[cc * CC + c] * Wbias[c * HH + h];
        g_Qm[cc * HH + h] = s;
    } else if (idx < 2193) {
        int h = idx - 2189;
        float s = 0.f;
        for (int c = 0; c < CC; c++) s += btv[c] * Wbias[c * HH + h];
        g_q0[h] = s;
    } else if (idx < 2241) {
        int q = idx - 2193; int g = q / 4, h = q % 4;
        float s = 0.f;
        for (int c = 0; c < CC; c++) s += Wrel[g * CC + c] * Wbias[c * HH + h];
        g_Wrb[q] = s;
    } else if (idx < 2245) {
        int h = idx - 2241;
        float s = 0.f;
        for (int c = 0; c < CC; c++) s += brel[c] * Wbias[c * HH + h];
        g_cb[h] = s + bbias[h];
    }
}

// ---------------- kernel 1: lang tokens -> M, c0, Vb ----------------
__global__ __launch_bounds__(128) void k_lang(const float* __restrict__ lang)
{
    const int bt = blockIdx.x;
    const int b = bt >> 6, t = bt & 63;
    const int tid = threadIdx.x;
    __shared__ float L[CC];
    L[tid] = lang[bt * CC + tid];
    __syncthreads();
    const int wid = tid >> 5, lane = tid & 31;
    for (int o = wid; o < 17; o += 4) {
        float s = 0.f;
        if (o < 12) {
            for (int c = lane; c < CC; c += 32) s += L[c] * g_P[c * GG + o];
        } else if (o == 12) {
            for (int c = lane; c < CC; c += 32) s += L[c] * g_pc[c];
        } else {
            int h = o - 13;
            for (int c = lane; c < CC; c += 32) s += L[c] * g_Qm[c * HH + h];
        }
        #pragma unroll
        for (int off = 16; off; off >>= 1) s += __shfl_xor_sync(0xffffffffu, s, off);
        if (lane == 0) {
            if (o < 12)       g_M[(b * GG + o) * TT + t] = s + g_p0[o];
            else if (o == 12) g_c0[b * TT + t] = s + g_pc0[0];
            else              g_Vb[(b * TT + t) * HH + (o - 13)] = s + g_q0[o - 13];
        }
    }
}

// ---------------- kernel 2: QKV projections + box sizes (16 rows/block) ----------------
__global__ __launch_bounds__(128) void k_qkv(
    const float* __restrict__ feat, const float* __restrict__ corners,
    const float* __restrict__ Wq, const float* __restrict__ bq,
    const float* __restrict__ Wk, const float* __restrict__ bk,
    const float* __restrict__ Wv, const float* __restrict__ bv)
{
    const int blk = blockIdx.x;
    const int tid = threadIdx.x;
    const int row0 = blk * 16;
    __shared__ float F[16][CC];
    #pragma unroll
    for (int r = 0; r < 16; r++) F[r][tid] = feat[(row0 + r) * CC + tid];
    __syncthreads();
    float aq[16], ak[16], av[16];
    #pragma unroll
    for (int r = 0; r < 16; r++) { aq[r] = bq[tid]; ak[r] = bk[tid]; av[r] = bv[tid]; }
    for (int cc = 0; cc < CC; cc++) {
        float wq = Wq[cc * CC + tid], wk = Wk[cc * CC + tid], wv = Wv[cc * CC + tid];
        #pragma unroll
        for (int r = 0; r < 16; r++) {
            float f = F[r][cc];
            aq[r] += f * wq; ak[r] += f * wk; av[r] += f * wv;
        }
    }
    const int h = tid >> 5, d = tid & 31;
    #pragma unroll
    for (int r = 0; r < 16; r++) {
        int bi = row0 + r; int b = bi >> 8, i = bi & 255;
        int o = ((b * HH + h) * NN + i) * DD + d;
        g_q[o] = aq[r]; g_v[o] = av[r];
        g_kT[((b * HH + h) * DD + d) * NN + i] = ak[r];
    }
    if (tid < 48) {
        int r = tid / 3, kd = tid % 3;
        int bi = row0 + r;
        float mx = -1e30f, mn = 1e30f;
        for (int cn = 0; cn < 8; cn++) {
            float v2 = corners[(bi * 8 + cn) * 3 + kd];
            mx = fmaxf(mx, v2); mn = fminf(mn, v2);
        }
        g_sizes[bi * 3 + kd] = mx - mn;
    }
}

// ---------------- kernel 2b: QK logits GEMM ----------------
// grid (NN/64, HH, BB), 256 threads = j. Q tile in smem, K column in regs.
__global__ __launch_bounds__(256) void k_logits()
{
    const int i0 = blockIdx.x * 64;
    const int h = blockIdx.y;
    const int b = blockIdx.z;
    const int tid = threadIdx.x;
    __shared__ float4 sQt[64 * 8];   // [i][d4]

    {
        const float4* qp = (const float4*)(g_q + ((size_t)(b * HH + h) * NN + i0) * DD);
        #pragma unroll
        for (int r = 0; r < 2; r++) sQt[tid + r * 256] = qp[tid + r * 256];
    }
    const int j = tid;
    float kr[DD];
    {
        const float* kT = g_kT + (size_t)(b * HH + h) * DD * NN + j;
        #pragma unroll
        for (int d = 0; d < DD; d++) kr[d] = kT[d * NN];
    }
    __syncthreads();
    float* lp = g_logits + ((size_t)(b * HH + h) * NN + i0) * NN + j;
    #pragma unroll 4
    for (int i = 0; i < 64; i++) {
        float dot = 0.f;
        #pragma unroll
        for (int d4 = 0; d4 < 8; d4++) {
            float4 qv = sQt[i * 8 + d4];
            dot += qv.x * kr[d4 * 4 + 0] + qv.y * kr[d4 * 4 + 1]
                 + qv.z * kr[d4 * 4 + 2] + qv.w * kr[d4 * 4 + 3];
        }
        lp[(size_t)i * NN] = dot * 0.17677669529663687f;  // 1/sqrt(32)
    }
}

// ---------------- kernel 3: fused main ----------------
__global__ __launch_bounds__(256, 4) void k_main(
    const float* __restrict__ centers,
    const float* __restrict__ Wo,
    const float* __restrict__ bo,
    float* __restrict__ out)
{
    const int i = blockIdx.x;
    const int b = blockIdx.y;
    const int tid = threadIdx.x;

    __shared__ float4 sCoef4[9 * 16];  // 9 merged score rows x 64 tokens
    __shared__ float4 sC0b4[16];       // folded per-block constant
    __shared__ float4 sVb4[TT];
    __shared__ float  sWrbF[9 * HH];   // folded bias coefficients [g][h]
    __shared__ float  sCbF[HH];        // folded bias constant
    __shared__ float  sCi[3], sSi[3];
    __shared__ float4 sE4[NN];
    __shared__ float  sRedM[8 * HH];
    __shared__ float  sRedS[8 * HH];
    __shared__ float  sAVf[8][CC];
    __shared__ float  sOF[CC];
    __shared__ float  sOP[2][CC];

    float* sCoef = (float*)sCoef4;
    float* sVb   = (float*)sVb4;
    float* sE    = (float*)sE4;

    const float* Mb = g_M + b * (GG * TT);

    // ---- phase A: loads ----
    for (int x = tid; x < 6 * TT; x += 256) sCoef[x] = Mb[x];
    sVb[tid] = g_Vb[b * TT * HH + tid];
    if (tid < 3) {
        sCi[tid] = centers[(b * NN + i) * 3 + tid];
        sSi[tid] = g_sizes[(b * NN + i) * 3 + tid];
    }
    __syncthreads();

    // ---- phase B: fold i-side into constants / merged rows ----
    if (tid < TT) {
        const int t = tid;
        float inv0 = __fdividef(1.f, sSi[0] + FEPS);
        float inv1 = __fdividef(1.f, sSi[1] + FEPS);
        float inv2 = __fdividef(1.f, sSi[2] + FEPS);
        float m6 = Mb[6 * TT + t],  m7 = Mb[7 * TT + t],  m8 = Mb[8 * TT + t];
        float m9 = Mb[9 * TT + t], m10 = Mb[10 * TT + t], m11 = Mb[11 * TT + t];
        float c0 = g_c0[b * TT + t]
                 - sCi[0] * sCoef[0 * TT + t]
                 - sCi[1] * sCoef[1 * TT + t]
                 - sCi[2] * sCoef[2 * TT + t]
                 - sSi[0] * m6 - sSi[1] * m7 - sSi[2] * m8;
        ((float*)sC0b4)[t] = c0;
        sCoef[6 * TT + t] = m6 + inv0 * m9;
        sCoef[7 * TT + t] = m7 + inv1 * m10;
        sCoef[8 * TT + t] = m8 + inv2 * m11;
    } else if (tid < TT + 36) {
        const int q = tid - TT; const int g = q >> 2, h = q & 3;
        float w = g_Wrb[g * HH + h];
        if (g >= 6) {
            float invs = __fdividef(1.f, sSi[g - 6] + FEPS);
            w += invs * g_Wrb[(g + 3) * HH + h];
        }
        sWrbF[q] = w;
    } else if (tid < TT + 40) {
        const int h = tid - TT - 36;
        float c = g_cb[h];
        #pragma unroll
        for (int kk = 0; kk < 3; kk++)
            c -= sCi[kk] * g_Wrb[kk * HH + h] + sSi[kk] * g_Wrb[(6 + kk) * HH + h];
        sCbF[h] = c;
    }
    __syncthreads();

    // ---- per-thread geometry (j = tid) ----
    const int j = tid;
    float cjx = centers[(b * NN + j) * 3 + 0];
    float cjy = centers[(b * NN + j) * 3 + 1];
    float cjz = centers[(b * NN + j) * 3 + 2];
    float rx = cjx - sCi[0], ry = cjy - sCi[1], rz = cjz - sCi[2];
    float r2all = rx * rx + ry * ry + rz * rz;
    float r2h   = rx * rx + ry * ry;
    float dist  = r2all * rsqrtf(r2all + 1e-30f);
    float horiz = r2h * rsqrtf(r2h + 1e-30f);
    float dl = __logf(dist + FEPS);
    float ce = __fdividef(rz, dist + FEPS);
    float sj0 = g_sizes[(b * NN + j) * 3 + 0];
    float sj1 = g_sizes[(b * NN + j) * 3 + 1];
    float sj2 = g_sizes[(b * NN + j) * 3 + 2];

    // 9 coefficient values (shared by score rows and folded bias rows)
    ull cv2[9];
    cv2[0] = pack2(cjx, cjx); cv2[1] = pack2(cjy, cjy); cv2[2] = pack2(cjz, cjz);
    cv2[3] = pack2(dl, dl);   cv2[4] = pack2(horiz, horiz); cv2[5] = pack2(ce, ce);
    cv2[6] = pack2(sj0, sj0); cv2[7] = pack2(sj1, sj1); cv2[8] = pack2(sj2, sj2);

    const uint32_t c0Addr   = (uint32_t)__cvta_generic_to_shared(sC0b4);
    const uint32_t coefAddr = (uint32_t)__cvta_generic_to_shared(sCoef4);
    const uint32_t vbAddr   = (uint32_t)__cvta_generic_to_shared(sVb4);
    const uint32_t wrbAddr  = (uint32_t)__cvta_generic_to_shared(sWrbF);

    // ---- token scores + online softmax: 4 chunks of 16 tokens ----
    float m = -1e30f, ssum = 0.f;
    ull aA = 0ull, aB = 0ull;   // packed alpha@Vb accumulators (h0,h1),(h2,h3)
    #pragma unroll
    for (int ch = 0; ch < 4; ch++) {
        ull sc2[8];
        #pragma unroll
        for (int t4 = 0; t4 < 4; t4++)
            LDS2(sc2[2 * t4], sc2[2 * t4 + 1], c0Addr + (ch * 4 + t4) * 16);
        #pragma unroll
        for (int g = 0; g < 9; g++) {
            #pragma unroll
            for (int t4 = 0; t4 < 4; t4++) {
                ull mA, mB;
                LDS2(mA, mB, coefAddr + (g * 16 + ch * 4 + t4) * 16);
                sc2[2 * t4]     = fma2(cv2[g], mA, sc2[2 * t4]);
                sc2[2 * t4 + 1] = fma2(cv2[g], mB, sc2[2 * t4 + 1]);
            }
        }
        float cm = -1e30f;
        #pragma unroll
        for (int k = 0; k < 8; k++) {
            float2 v = unpack2(sc2[k]);
            cm = fmaxf(cm, fmaxf(v.x, v.y));
        }
        float newm = fmaxf(m, cm);
        float scale = __expf(m - newm);
        ssum *= scale;
        ull s2 = pack2(scale, scale);
        aA = mul2(aA, s2); aB = mul2(aB, s2);
        #pragma unroll
        for (int k = 0; k < 8; k++) {
            float2 v = unpack2(sc2[k]);
            float e0 = __expf(v.x - newm);
            float e1 = __expf(v.y - newm);
            ssum += e0 + e1;
            ull vA, vB;
            LDS2(vA, vB, vbAddr + (ch * 16 + 2 * k) * 16);
            ull e02 = pack2(e0, e0);
            aA = fma2(e02, vA, aA); aB = fma2(e02, vB, aB);
            LDS2(vA, vB, vbAddr + (ch * 16 + 2 * k + 1) * 16);
            ull e12 = pack2(e1, e1);
            aA = fma2(e12, vA, aA); aB = fma2(e12, vB, aB);
        }
        m = newm;
    }
    float inv = __fdividef(1.f, ssum);
    float2 a01 = unpack2(aA), a23 = unpack2(aB);

    // ---- bias per head (folded 9-row matvec) + precomputed logits ----
    ull bA = pack2(sCbF[0], sCbF[1]);
    ull bB = pack2(sCbF[2], sCbF[3]);
    #pragma unroll
    for (int g = 0; g < 9; g++) {
        ull wA, wB;
        LDS2(wA, wB, wrbAddr + g * 16);
        bA = fma2(cv2[g], wA, bA);
        bB = fma2(cv2[g], wB, bB);
    }
    float2 b01 = unpack2(bA), b23 = unpack2(bB);
    float lg[HH];
    {
        const float* lp = g_logits + ((size_t)(b * HH) * NN + i) * NN + j;
        lg[0] = lp[0]                     + b01.x + a01.x * inv;
        lg[1] = lp[(size_t)NN * NN]       + b01.y + a01.y * inv;
        lg[2] = lp[(size_t)2 * NN * NN]   + b23.x + a23.x * inv;
        lg[3] = lp[(size_t)3 * NN * NN]   + b23.y + a23.y * inv;
    }

    // ---- block softmax over j per head ----
    const int wid = tid >> 5, lane = tid & 31;
    float m4[HH];
    #pragma unroll
    for (int h = 0; h < HH; h++) m4[h] = lg[h];
    #pragma unroll
    for (int off = 16; off; off >>= 1) {
        #pragma unroll
        for (int h = 0; h < HH; h++)
            m4[h] = fmaxf(m4[h], __shfl_xor_sync(0xffffffffu, m4[h], off));
    }
    if (lane == 0) {
        #pragma unroll
        for (int h = 0; h < HH; h++) sRedM[wid * 4 + h] = m4[h];
    }
    __syncthreads();
    float hmax[HH];
    #pragma unroll
    for (int h = 0; h < HH; h++) {
        float mm = sRedM[h];
        #pragma unroll
        for (int w = 1; w < 8; w++) mm = fmaxf(mm, sRedM[w * 4 + h]);
        hmax[h] = mm;
    }
    float e4[HH], s4[HH];
    #pragma unroll
    for (int h = 0; h < HH; h++) { e4[h] = __expf(lg[h] - hmax[h]); s4[h] = e4[h]; }
    sE4[tid] = make_float4(e4[0], e4[1], e4[2], e4[3]);
    #pragma unroll
    for (int off = 16; off; off >>= 1) {
        #pragma unroll
        for (int h = 0; h < HH; h++)
            s4[h] += __shfl_xor_sync(0xffffffffu, s4[h], off);
    }
    __syncthreads();
    if (lane == 0) {
        #pragma unroll
        for (int h = 0; h < HH; h++) sRedS[wid * 4 + h] = s4[h];
    }
    __syncthreads();

    // ---- attention output: AV with packed fma ----
    {
        const int h = lane >> 3, d4 = lane & 7;
        const float* vp = g_v + (size_t)(b * HH + h) * NN * DD + d4 * 4;
        ull accA = 0ull, accB = 0ull;
        #pragma unroll 8
        for (int jj = 0; jj < 32; jj++) {
            int j2 = wid * 32 + jj;
            float e = sE[j2 * 4 + h];
            ull vA, vB;
            LDG2(vA, vB, vp + (size_t)j2 * DD);
            ull e2 = pack2(e, e);
            accA = fma2(e2, vA, accA);
            accB = fma2(e2, vB, accB);
        }
        ull* dst = (ull*)&sAVf[wid][lane * 4];
        dst[0] = accA; dst[1] = accB;
    }
    __syncthreads();
    if (tid < CC) {
        const int h = tid >> 5, d = tid & 31;
        float s = 0.f;
        #pragma unroll
        for (int w = 0; w < 8; w++) s += sAVf[w][h * 32 + d];
        float denom = sRedS[h];
        #pragma unroll
        for (int w = 1; w < 8; w++) denom += sRedS[w * 4 + h];
        sOF[tid] = __fdividef(s, denom);
    }
    __syncthreads();

    // ---- output projection ----
    {
        const int c = tid & 127;
        const int half = tid >> 7;
        const float* wp = Wo + (half * 64) * CC + c;
        float acc2 = 0.f;
        #pragma unroll 8
        for (int cc2 = 0; cc2 < 64; cc2++)
            acc2 += sOF[half * 64 + cc2] * wp[cc2 * CC];
        sOP[half][c] = acc2;
    }
    __syncthreads();
    if (tid < CC)
        out[(b * NN + i) * CC + tid] = bo[tid] + sOP[0][tid] + sOP[1][tid];
}

// ---------------- launch ----------------
extern "C" void kernel_launch(void* const* d_in, const int* in_sizes, int n_in,
                              void* d_out, int out_size)
{
    const float* feat    = (const float*)d_in[0];
    const float* centers = (const float*)d_in[1];
    const float* corners = (const float*)d_in[2];
    const float* lang    = (const float*)d_in[3];
    const float* Wq    = (const float*)d_in[4];
    const float* bq    = (const float*)d_in[5];
    const float* Wk    = (const float*)d_in[6];
    const float* bk    = (const float*)d_in[7];
    const float* Wv    = (const float*)d_in[8];
    const float* bv    = (const float*)d_in[9];
    const float* Wo    = (const float*)d_in[10];
    const float* bo    = (const float*)d_in[11];
    const float* Wrel  = (const float*)d_in[12];
    const float* brel  = (const float*)d_in[13];
    const float* Wtk   = (const float*)d_in[14];
    const float* btk   = (const float*)d_in[15];
    const float* Wtv   = (const float*)d_in[16];
    const float* btv   = (const float*)d_in[17];
    const float* Wbias = (const float*)d_in[18];
    const float* bbias = (const float*)d_in[19];

    k_combos<<<9, 256>>>(Wtk, btk, Wtv, btv, Wrel, brel, Wbias, bbias);
    k_lang<<<BB * TT, 128>>>(lang);
    k_qkv<<<BB * NN / 16, 128>>>(feat, corners, Wq, bq, Wk, bk, Wv, bv);
    k_logits<<<dim3(NN / 64, HH, BB), 256>>>();
    k_main<<<dim3(NN, BB), 256>>>(centers, Wo, bo, (float*)d_out);
}

// round 6
// speedup vs baseline: 1.8554x; 1.1393x over previous
#include <cuda_runtime.h>
#include <math.h>
#include <stdint.h>

#define BB 8
#define NN 256
#define CC 128
#define TT 64
#define HH 4
#define GG 12
#define DD 32
#define FEPS 1e-6f
#define LOG2E 1.4426950408889634f

typedef unsigned long long ull;

// ---- f32x2 packed-math helpers ----
__device__ __forceinline__ ull pack2(float lo, float hi) {
    ull d;
    asm("mov.b64 %0, {%1, %2};" : "=l"(d)
        : "r"(__float_as_uint(lo)), "r"(__float_as_uint(hi)));
    return d;
}
__device__ __forceinline__ float2 unpack2(ull s) {
    uint32_t a, b;
    asm("mov.b64 {%0, %1}, %2;" : "=r"(a), "=r"(b) : "l"(s));
    return make_float2(__uint_as_float(a), __uint_as_float(b));
}
__device__ __forceinline__ ull fma2(ull a, ull b, ull c) {
    ull d;
    asm("fma.rn.f32x2 %0, %1, %2, %3;" : "=l"(d) : "l"(a), "l"(b), "l"(c));
    return d;
}
__device__ __forceinline__ float ex2(float x) {
    float y;
    asm("ex2.approx.ftz.f32 %0, %1;" : "=f"(y) : "f"(x));
    return y;
}
#define LDS2(a, b, addr) \
    asm volatile("ld.shared.v2.u64 {%0, %1}, [%2];" : "=l"(a), "=l"(b) : "r"(addr))
#define LDG2(a, b, p) \
    asm volatile("ld.global.nc.v2.u64 {%0, %1}, [%2];" : "=l"(a), "=l"(b) : "l"(p))

// ---------------- scratch ----------------
__device__ float g_P[CC * GG];
__device__ float g_p0[GG];
__device__ float g_pc[CC];
__device__ float g_pc0[1];
__device__ float g_Qm[CC * HH];
__device__ float g_q0[HH];
__device__ float g_Wrb[GG * HH];
__device__ float g_cb[HH];
__device__ float g_M[BB * GG * TT];
__device__ float g_c0[BB * TT];
__device__ float g_Vb[BB * TT * HH];
__device__ float g_q[BB * HH * NN * DD];
__device__ float g_kT[BB * HH * DD * NN];      // [b][h][d][j]
__device__ float g_v[BB * HH * NN * DD];
__device__ float g_sizes[BB * NN * 3];
__device__ float g_logits[BB * HH * NN * NN];  // [b][h][i][j] (scaled QK * LOG2E)

// ---------------- kernel 0: weight combos ----------------
__global__ void k_combos(const float* __restrict__ Wtk, const float* __restrict__ btk,
                         const float* __restrict__ Wtv, const float* __restrict__ btv,
                         const float* __restrict__ Wrel, const float* __restrict__ brel,
                         const float* __restrict__ Wbias, const float* __restrict__ bbias)
{
    const float isC = 0.08838834764831845f;  // 1/sqrt(128)
    int idx = blockIdx.x * blockDim.x + threadIdx.x;
    if (idx < 1536) {
        int cc = idx / 12, g = idx % 12;
        float s = 0.f;
        for (int c = 0; c < CC; c++) s += Wtk[cc * CC + c] * Wrel[g * CC + c];
        g_P[idx] = s * isC;
    } else if (idx < 1548) {
        int g = idx - 1536;
        float s = 0.f;
        for (int c = 0; c < CC; c++) s += btk[c] * Wrel[g * CC + c];
        g_p0[g] = s * isC;
    } else if (idx < 1676) {
        int cc = idx - 1548;
        float s = 0.f;
        for (int c = 0; c < CC; c++) s += Wtk[cc * CC + c] * brel[c];
        g_pc[cc] = s * isC;
    } else if (idx == 1676) {
        float s = 0.f;
        for (int c = 0; c < CC; c++) s += btk[c] * brel[c];
        g_pc0[0] = s * isC;
    } else if (idx < 2189) {
        int q = idx - 1677; int cc = q / 4, h = q % 4;
        float s = 0.f;
        for (int c = 0; c < CC; c++) s += Wtv[cc * CC + c] * Wbias[c * HH + h];
        g_Qm[cc * HH + h] = s;
    } else if (idx < 2193) {
        int h = idx - 2189;
        float s = 0.f;
        for (int c = 0; c < CC; c++) s += btv[c] * Wbias[c * HH + h];
        g_q0[h] = s;
    } else if (idx < 2241) {
        int q = idx - 2193; int g = q / 4, h = q % 4;
        float s = 0.f;
        for (int c = 0; c < CC; c++) s += Wrel[g * CC + c] * Wbias[c * HH + h];
        g_Wrb[q] = s;
    } else if (idx < 2245) {
        int h = idx - 2241;
        float s = 0.f;
        for (int c = 0; c < CC; c++) s += brel[c] * Wbias[c * HH + h];
        g_cb[h] = s + bbias[h];
    }
}

// ---------------- kernel 1: lang tokens -> M, c0, Vb ----------------
__global__ __launch_bounds__(128) void k_lang(const float* __restrict__ lang)
{
    const int bt = blockIdx.x;
    const int b = bt >> 6, t = bt & 63;
    const int tid = threadIdx.x;
    __shared__ float L[CC];
    L[tid] = lang[bt * CC + tid];
    __syncthreads();
    const int wid = tid >> 5, lane = tid & 31;
    for (int o = wid; o < 17; o += 4) {
        float s = 0.f;
        if (o < 12) {
            for (int c = lane; c < CC; c += 32) s += L[c] * g_P[c * GG + o];
        } else if (o == 12) {
            for (int c = lane; c < CC; c += 32) s += L[c] * g_pc[c];
        } else {
            int h = o - 13;
            for (int c = lane; c < CC; c += 32) s += L[c] * g_Qm[c * HH + h];
        }
        #pragma unroll
        for (int off = 16; off; off >>= 1) s += __shfl_xor_sync(0xffffffffu, s, off);
        if (lane == 0) {
            if (o < 12)       g_M[(b * GG + o) * TT + t] = s + g_p0[o];
            else if (o == 12) g_c0[b * TT + t] = s + g_pc0[0];
            else              g_Vb[(b * TT + t) * HH + (o - 13)] = s + g_q0[o - 13];
        }
    }
}

// ---------------- kernel 2: QKV projections + box sizes ----------------
__global__ __launch_bounds__(256) void k_qkv(
    const float* __restrict__ feat, const float* __restrict__ corners,
    const float* __restrict__ Wq, const float* __restrict__ bq,
    const float* __restrict__ Wk, const float* __restrict__ bk,
    const float* __restrict__ Wv, const float* __restrict__ bv)
{
    const int blk = blockIdx.x;
    const int tid = threadIdx.x;
    const int half = tid >> 7;        // which 8-row group
    const int ch = tid & 127;         // output channel
    const int rbase = blk * 16;
    __shared__ float F[16][CC];
    for (int x = tid; x < 16 * CC; x += 256)
        F[x >> 7][x & 127] = feat[rbase * CC + x];
    __syncthreads();

    float aq[8], ak[8], av[8];
    #pragma unroll
    for (int r = 0; r < 8; r++) { aq[r] = bq[ch]; ak[r] = bk[ch]; av[r] = bv[ch]; }
    for (int cc = 0; cc < CC; cc++) {
        float wq = Wq[cc * CC + ch], wk = Wk[cc * CC + ch], wv = Wv[cc * CC + ch];
        #pragma unroll
        for (int r = 0; r < 8; r++) {
            float f = F[half * 8 + r][cc];
            aq[r] += f * wq; ak[r] += f * wk; av[r] += f * wv;
        }
    }
    const int h = ch >> 5, d = ch & 31;
    #pragma unroll
    for (int r = 0; r < 8; r++) {
        int bi = rbase + half * 8 + r; int b = bi >> 8, i = bi & 255;
        int o = ((b * HH + h) * NN + i) * DD + d;
        g_q[o] = aq[r]; g_v[o] = av[r];
        g_kT[((b * HH + h) * DD + d) * NN + i] = ak[r];
    }
    if (tid < 48) {
        int r = tid / 3, kd = tid % 3;
        int bi = rbase + r;
        float mx = -1e30f, mn = 1e30f;
        for (int cn = 0; cn < 8; cn++) {
            float v2 = corners[(bi * 8 + cn) * 3 + kd];
            mx = fmaxf(mx, v2); mn = fminf(mn, v2);
        }
        g_sizes[bi * 3 + kd] = mx - mn;
    }
}

// ---------------- kernel 2b: QK logits GEMM (scaled by LOG2E) ----------------
__global__ __launch_bounds__(256) void k_logits()
{
    const int i0 = blockIdx.x * 32;
    const int h = blockIdx.y;
    const int b = blockIdx.z;
    const int tid = threadIdx.x;
    __shared__ float4 sQt[32 * 8];   // [i][d4]

    {
        const float4* qp = (const float4*)(g_q + ((size_t)(b * HH + h) * NN + i0) * DD);
        sQt[tid] = qp[tid];
    }
    const int j = tid;
    float kr[DD];
    {
        const float* kT = g_kT + (size_t)(b * HH + h) * DD * NN + j;
        #pragma unroll
        for (int d = 0; d < DD; d++) kr[d] = kT[d * NN];
    }
    __syncthreads();
    const float SC = 0.17677669529663687f * LOG2E;  // 1/sqrt(32) * log2(e)
    float* lp = g_logits + ((size_t)(b * HH + h) * NN + i0) * NN + j;
    #pragma unroll 4
    for (int i = 0; i < 32; i++) {
        float dot = 0.f;
        #pragma unroll
        for (int d4 = 0; d4 < 8; d4++) {
            float4 qv = sQt[i * 8 + d4];
            dot += qv.x * kr[d4 * 4 + 0] + qv.y * kr[d4 * 4 + 1]
                 + qv.z * kr[d4 * 4 + 2] + qv.w * kr[d4 * 4 + 3];
        }
        lp[(size_t)i * NN] = dot * SC;
    }
}

// ---------------- kernel 3: fused main (log2 domain, no max-sub) ----------------
__global__ __launch_bounds__(256, 4) void k_main(
    const float* __restrict__ centers,
    const float* __restrict__ Wo,
    const float* __restrict__ bo,
    float* __restrict__ out)
{
    const int i = blockIdx.x;
    const int b = blockIdx.y;
    const int tid = threadIdx.x;

    __shared__ float4 sCoef4[9 * 16];  // 9 merged score rows x 64 tokens (x LOG2E)
    __shared__ float4 sC0b4[16];       // folded per-block constant (x LOG2E)
    __shared__ float4 sVb4[TT];        // Vb (RAW — softmax weights are base-invariant)
    __shared__ float  sWrbF[9 * HH];   // folded bias coefficients x LOG2E
    __shared__ float  sCbF[HH];        // folded bias constant x LOG2E
    __shared__ float  sCi[3], sSi[3];
    __shared__ float4 sE4[NN];
    __shared__ float  sRedS[8 * HH];
    __shared__ float  sAVf[8][CC];
    __shared__ float  sOF[CC];
    __shared__ float  sOP[2][CC];

    float* sCoef = (float*)sCoef4;
    float* sVb   = (float*)sVb4;
    float* sE    = (float*)sE4;

    const float* Mb = g_M + b * (GG * TT);

    // ---- phase A: loads ----
    for (int x = tid; x < 6 * TT; x += 256) sCoef[x] = Mb[x] * LOG2E;
    sVb[tid] = g_Vb[b * TT * HH + tid];             // RAW (fix: no LOG2E here)
    if (tid < 3) {
        sCi[tid] = centers[(b * NN + i) * 3 + tid];
        sSi[tid] = g_sizes[(b * NN + i) * 3 + tid];
    }
    __syncthreads();

    // ---- phase B: fold i-side into constants / merged rows ----
    if (tid < TT) {
        const int t = tid;
        float inv0 = __fdividef(1.f, sSi[0] + FEPS);
        float inv1 = __fdividef(1.f, sSi[1] + FEPS);
        float inv2 = __fdividef(1.f, sSi[2] + FEPS);
        float m6 = Mb[6 * TT + t],  m7 = Mb[7 * TT + t],  m8 = Mb[8 * TT + t];
        float m9 = Mb[9 * TT + t], m10 = Mb[10 * TT + t], m11 = Mb[11 * TT + t];
        float c0 = g_c0[b * TT + t] * LOG2E
                 - sCi[0] * sCoef[0 * TT + t]
                 - sCi[1] * sCoef[1 * TT + t]
                 - sCi[2] * sCoef[2 * TT + t]
                 - (sSi[0] * m6 + sSi[1] * m7 + sSi[2] * m8) * LOG2E;
        ((float*)sC0b4)[t] = c0;
        sCoef[6 * TT + t] = (m6 + inv0 * m9) * LOG2E;
        sCoef[7 * TT + t] = (m7 + inv1 * m10) * LOG2E;
        sCoef[8 * TT + t] = (m8 + inv2 * m11) * LOG2E;
    } else if (tid < TT + 36) {
        const int q = tid - TT; const int g = q >> 2, h = q & 3;
        float w = g_Wrb[g * HH + h];
        if (g >= 6) {
            float invs = __fdividef(1.f, sSi[g - 6] + FEPS);
            w += invs * g_Wrb[(g + 3) * HH + h];
        }
        sWrbF[q] = w * LOG2E;
    } else if (tid < TT + 40) {
        const int h = tid - TT - 36;
        float c = g_cb[h];
        #pragma unroll
        for (int kk = 0; kk < 3; kk++)
            c -= sCi[kk] * g_Wrb[kk * HH + h] + sSi[kk] * g_Wrb[(6 + kk) * HH + h];
        sCbF[h] = c * LOG2E;
    }
    __syncthreads();

    // ---- per-thread geometry (j = tid) ----
    const int j = tid;
    float cjx = centers[(b * NN + j) * 3 + 0];
    float cjy = centers[(b * NN + j) * 3 + 1];
    float cjz = centers[(b * NN + j) * 3 + 2];
    float rx = cjx - sCi[0], ry = cjy - sCi[1], rz = cjz - sCi[2];
    float r2all = rx * rx + ry * ry + rz * rz;
    float r2h   = rx * rx + ry * ry;
    float dist  = r2all * rsqrtf(r2all + 1e-30f);
    float horiz = r2h * rsqrtf(r2h + 1e-30f);
    float dl = __logf(dist + FEPS);
    float ce = __fdividef(rz, dist + FEPS);
    float sj0 = g_sizes[(b * NN + j) * 3 + 0];
    float sj1 = g_sizes[(b * NN + j) * 3 + 1];
    float sj2 = g_sizes[(b * NN + j) * 3 + 2];

    ull cv2[9];
    cv2[0] = pack2(cjx, cjx); cv2[1] = pack2(cjy, cjy); cv2[2] = pack2(cjz, cjz);
    cv2[3] = pack2(dl, dl);   cv2[4] = pack2(horiz, horiz); cv2[5] = pack2(ce, ce);
    cv2[6] = pack2(sj0, sj0); cv2[7] = pack2(sj1, sj1); cv2[8] = pack2(sj2, sj2);

    const uint32_t c0Addr   = (uint32_t)__cvta_generic_to_shared(sC0b4);
    const uint32_t coefAddr = (uint32_t)__cvta_generic_to_shared(sCoef4);
    const uint32_t vbAddr   = (uint32_t)__cvta_generic_to_shared(sVb4);
    const uint32_t wrbAddr  = (uint32_t)__cvta_generic_to_shared(sWrbF);

    // ---- token scores + softmax accumulation (no max-sub, log2 domain) ----
    float ssum = 0.f;
    ull aA = 0ull, aB = 0ull;
    #pragma unroll
    for (int ch = 0; ch < 4; ch++) {
        ull sc2[8];
        #pragma unroll
        for (int t4 = 0; t4 < 4; t4++)
            LDS2(sc2[2 * t4], sc2[2 * t4 + 1], c0Addr + (ch * 4 + t4) * 16);
        #pragma unroll
        for (int g = 0; g < 9; g++) {
            #pragma unroll
            for (int t4 = 0; t4 < 4; t4++) {
                ull mA, mB;
                LDS2(mA, mB, coefAddr + (g * 16 + ch * 4 + t4) * 16);
                sc2[2 * t4]     = fma2(cv2[g], mA, sc2[2 * t4]);
                sc2[2 * t4 + 1] = fma2(cv2[g], mB, sc2[2 * t4 + 1]);
            }
        }
        #pragma unroll
        for (int k = 0; k < 8; k++) {
            float2 v = unpack2(sc2[k]);
            float e0 = ex2(v.x);
            float e1 = ex2(v.y);
            ssum += e0 + e1;
            ull vA, vB;
            LDS2(vA, vB, vbAddr + (ch * 16 + 2 * k) * 16);
            ull e02 = pack2(e0, e0);
            aA = fma2(e02, vA, aA); aB = fma2(e02, vB, aB);
            LDS2(vA, vB, vbAddr + (ch * 16 + 2 * k + 1) * 16);
            ull e12 = pack2(e1, e1);
            aA = fma2(e12, vA, aA); aB = fma2(e12, vB, aB);
        }
    }
    float inv = __fdividef(1.f, ssum);
    float2 a01 = unpack2(aA), a23 = unpack2(aB);

    // ---- bias per head (folded, log2 domain) + precomputed logits ----
    ull bA = pack2(sCbF[0], sCbF[1]);
    ull bB = pack2(sCbF[2], sCbF[3]);
    #pragma unroll
    for (int g = 0; g < 9; g++) {
        ull wA, wB;
        LDS2(wA, wB, wrbAddr + g * 16);
        bA = fma2(cv2[g], wA, bA);
        bB = fma2(cv2[g], wB, bB);
    }
    float2 b01 = unpack2(bA), b23 = unpack2(bB);
    float invL = inv * LOG2E;   // single LOG2E application for the ctx term
    float lg[HH];
    {
        const float* lp = g_logits + ((size_t)(b * HH) * NN + i) * NN + j;
        lg[0] = lp[0]                   + b01.x + a01.x * invL;
        lg[1] = lp[(size_t)NN * NN]     + b01.y + a01.y * invL;
        lg[2] = lp[(size_t)2 * NN * NN] + b23.x + a23.x * invL;
        lg[3] = lp[(size_t)3 * NN * NN] + b23.y + a23.y * invL;
    }

    // ---- attention softmax over j (no max-sub) ----
    const int wid = tid >> 5, lane = tid & 31;
    float e4[HH], s4[HH];
    #pragma unroll
    for (int h = 0; h < HH; h++) { e4[h] = ex2(lg[h]); s4[h] = e4[h]; }
    sE4[tid] = make_float4(e4[0], e4[1], e4[2], e4[3]);
    #pragma unroll
    for (int off = 16; off; off >>= 1) {
        #pragma unroll
        for (int h = 0; h < HH; h++)
            s4[h] += __shfl_xor_sync(0xffffffffu, s4[h], off);
    }
    if (lane == 0) {
        #pragma unroll
        for (int h = 0; h < HH; h++) sRedS[wid * 4 + h] = s4[h];
    }
    __syncthreads();

    // ---- attention output: AV with packed fma ----
    {
        const int h = lane >> 3, d4 = lane & 7;
        const float* vp = g_v + (size_t)(b * HH + h) * NN * DD + d4 * 4;
        ull accA = 0ull, accB = 0ull;
        #pragma unroll 8
        for (int jj = 0; jj < 32; jj++) {
            int j2 = wid * 32 + jj;
            float e = sE[j2 * 4 + h];
            ull vA, vB;
            LDG2(vA, vB, vp + (size_t)j2 * DD);
            ull e2 = pack2(e, e);
            accA = fma2(e2, vA, accA);
            accB = fma2(e2, vB, accB);
        }
        ull* dst = (ull*)&sAVf[wid][lane * 4];
        dst[0] = accA; dst[1] = accB;
    }
    __syncthreads();
    if (tid < CC) {
        const int h = tid >> 5, d = tid & 31;
        float s = 0.f;
        #pragma unroll
        for (int w = 0; w < 8; w++) s += sAVf[w][h * 32 + d];
        float denom = sRedS[h];
        #pragma unroll
        for (int w = 1; w < 8; w++) denom += sRedS[w * 4 + h];
        sOF[tid] = __fdividef(s, denom);
    }
    __syncthreads();

    // ---- output projection ----
    {
        const int c = tid & 127;
        const int half = tid >> 7;
        const float* wp = Wo + (half * 64) * CC + c;
        float acc2 = 0.f;
        #pragma unroll 8
        for (int cc2 = 0; cc2 < 64; cc2++)
            acc2 += sOF[half * 64 + cc2] * wp[cc2 * CC];
        sOP[half][c] = acc2;
    }
    __syncthreads();
    if (tid < CC)
        out[(b * NN + i) * CC + tid] = bo[tid] + sOP[0][tid] + sOP[1][tid];
}

// ---------------- launch ----------------
extern "C" void kernel_launch(void* const* d_in, const int* in_sizes, int n_in,
                              void* d_out, int out_size)
{
    const float* feat    = (const float*)d_in[0];
    const float* centers = (const float*)d_in[1];
    const float* corners = (const float*)d_in[2];
    const float* lang    = (const float*)d_in[3];
    const float* Wq    = (const float*)d_in[4];
    const float* bq    = (const float*)d_in[5];
    const float* Wk    = (const float*)d_in[6];
    const float* bk    = (const float*)d_in[7];
    const float* Wv    = (const float*)d_in[8];
    const float* bv    = (const float*)d_in[9];
    const float* Wo    = (const float*)d_in[10];
    const float* bo    = (const float*)d_in[11];
    const float* Wrel  = (const float*)d_in[12];
    const float* brel  = (const float*)d_in[13];
    const float* Wtk   = (const float*)d_in[14];
    const float* btk   = (const float*)d_in[15];
    const float* Wtv   = (const float*)d_in[16];
    const float* btv   = (const float*)d_in[17];
    const float* Wbias = (const float*)d_in[18];
    const float* bbias = (const float*)d_in[19];

    k_combos<<<9, 256>>>(Wtk, btk, Wtv, btv, Wrel, brel, Wbias, bbias);
    k_lang<<<BB * TT, 128>>>(lang);
    k_qkv<<<BB * NN / 16, 256>>>(feat, corners, Wq, bq, Wk, bk, Wv, bv);
    k_logits<<<dim3(NN / 32, HH, BB), 256>>>();
    k_main<<<dim3(NN, BB), 256>>>(centers, Wo, bo, (float*)d_out);
}

// round 7
// speedup vs baseline: 2.1107x; 1.1376x over previous
#include <cuda_runtime.h>
#include <math.h>
#include <stdint.h>

#define BB 8
#define NN 256
#define CC 128
#define TT 64
#define HH 4
#define GG 12
#define DD 32
#define FEPS 1e-6f
#define LOG2E 1.4426950408889634f

typedef unsigned long long ull;

// ---- f32x2 packed-math helpers ----
__device__ __forceinline__ ull pack2(float lo, float hi) {
    ull d;
    asm("mov.b64 %0, {%1, %2};" : "=l"(d)
        : "r"(__float_as_uint(lo)), "r"(__float_as_uint(hi)));
    return d;
}
__device__ __forceinline__ float2 unpack2(ull s) {
    uint32_t a, b;
    asm("mov.b64 {%0, %1}, %2;" : "=r"(a), "=r"(b) : "l"(s));
    return make_float2(__uint_as_float(a), __uint_as_float(b));
}
__device__ __forceinline__ ull fma2(ull a, ull b, ull c) {
    ull d;
    asm("fma.rn.f32x2 %0, %1, %2, %3;" : "=l"(d) : "l"(a), "l"(b), "l"(c));
    return d;
}
__device__ __forceinline__ float ex2(float x) {
    float y;
    asm("ex2.approx.ftz.f32 %0, %1;" : "=f"(y) : "f"(x));
    return y;
}
#define LDS2(a, b, addr) \
    asm volatile("ld.shared.v2.u64 {%0, %1}, [%2];" : "=l"(a), "=l"(b) : "r"(addr))
#define LDG2(a, b, p) \
    asm volatile("ld.global.nc.v2.u64 {%0, %1}, [%2];" : "=l"(a), "=l"(b) : "l"(p))

// ---------------- scratch ----------------
__device__ float g_P[CC * GG];
__device__ float g_p0[GG];
__device__ float g_pc[CC];
__device__ float g_pc0[1];
__device__ float g_Qm[CC * HH];
__device__ float g_q0[HH];
__device__ float g_Wrb[GG * HH];
__device__ float g_cb[HH];
__device__ float g_M[BB * GG * TT];
__device__ float g_c0[BB * TT];
__device__ float g_Vb[BB * TT * HH];
__device__ float g_q[BB * HH * NN * DD];
__device__ float g_kT[BB * HH * DD * NN];      // [b][h][d][j]
__device__ float g_v[BB * HH * NN * DD];
__device__ float g_sizes[BB * NN * 3];
__device__ float g_logits[BB * HH * NN * NN];  // [b][h][i][j] (scaled QK * LOG2E)

// ---------------- kernel 0: weight combos ----------------
__global__ void k_combos(const float* __restrict__ Wtk, const float* __restrict__ btk,
                         const float* __restrict__ Wtv, const float* __restrict__ btv,
                         const float* __restrict__ Wrel, const float* __restrict__ brel,
                         const float* __restrict__ Wbias, const float* __restrict__ bbias)
{
    const float isC = 0.08838834764831845f;  // 1/sqrt(128)
    int idx = blockIdx.x * blockDim.x + threadIdx.x;
    if (idx < 1536) {
        int cc = idx / 12, g = idx % 12;
        float s = 0.f;
        for (int c = 0; c < CC; c++) s += Wtk[cc * CC + c] * Wrel[g * CC + c];
        g_P[idx] = s * isC;
    } else if (idx < 1548) {
        int g = idx - 1536;
        float s = 0.f;
        for (int c = 0; c < CC; c++) s += btk[c] * Wrel[g * CC + c];
        g_p0[g] = s * isC;
    } else if (idx < 1676) {
        int cc = idx - 1548;
        float s = 0.f;
        for (int c = 0; c < CC; c++) s += Wtk[cc * CC + c] * brel[c];
        g_pc[cc] = s * isC;
    } else if (idx == 1676) {
        float s = 0.f;
        for (int c = 0; c < CC; c++) s += btk[c] * brel[c];
        g_pc0[0] = s * isC;
    } else if (idx < 2189) {
        int q = idx - 1677; int cc = q / 4, h = q % 4;
        float s = 0.f;
        for (int c = 0; c < CC; c++) s += Wtv[cc * CC + c] * Wbias[c * HH + h];
        g_Qm[cc * HH + h] = s;
    } else if (idx < 2193) {
        int h = idx - 2189;
        float s = 0.f;
        for (int c = 0; c < CC; c++) s += btv[c] * Wbias[c * HH + h];
        g_q0[h] = s;
    } else if (idx < 2241) {
        int q = idx - 2193; int g = q / 4, h = q % 4;
        float s = 0.f;
        for (int c = 0; c < CC; c++) s += Wrel[g * CC + c] * Wbias[c * HH + h];
        g_Wrb[q] = s;
    } else if (idx < 2245) {
        int h = idx - 2241;
        float s = 0.f;
        for (int c = 0; c < CC; c++) s += brel[c] * Wbias[c * HH + h];
        g_cb[h] = s + bbias[h];
    }
}

// ---------------- kernel 1: lang tokens -> M, c0, Vb ----------------
__global__ __launch_bounds__(128) void k_lang(const float* __restrict__ lang)
{
    const int bt = blockIdx.x;
    const int b = bt >> 6, t = bt & 63;
    const int tid = threadIdx.x;
    __shared__ float L[CC];
    L[tid] = lang[bt * CC + tid];
    __syncthreads();
    const int wid = tid >> 5, lane = tid & 31;
    for (int o = wid; o < 17; o += 4) {
        float s = 0.f;
        if (o < 12) {
            for (int c = lane; c < CC; c += 32) s += L[c] * g_P[c * GG + o];
        } else if (o == 12) {
            for (int c = lane; c < CC; c += 32) s += L[c] * g_pc[c];
        } else {
            int h = o - 13;
            for (int c = lane; c < CC; c += 32) s += L[c] * g_Qm[c * HH + h];
        }
        #pragma unroll
        for (int off = 16; off; off >>= 1) s += __shfl_xor_sync(0xffffffffu, s, off);
        if (lane == 0) {
            if (o < 12)       g_M[(b * GG + o) * TT + t] = s + g_p0[o];
            else if (o == 12) g_c0[b * TT + t] = s + g_pc0[0];
            else              g_Vb[(b * TT + t) * HH + (o - 13)] = s + g_q0[o - 13];
        }
    }
}

// ---------------- kernel 2: QKV projections + box sizes ----------------
// 256 blocks x 256 threads; 8 feat rows/block, 4 rows per thread-half.
__global__ __launch_bounds__(256) void k_qkv(
    const float* __restrict__ feat, const float* __restrict__ corners,
    const float* __restrict__ Wq, const float* __restrict__ bq,
    const float* __restrict__ Wk, const float* __restrict__ bk,
    const float* __restrict__ Wv, const float* __restrict__ bv)
{
    const int blk = blockIdx.x;
    const int tid = threadIdx.x;
    const int half = tid >> 7;
    const int ch = tid & 127;
    const int rbase = blk * 8;
    __shared__ float F[8][CC];
    for (int x = tid; x < 8 * CC; x += 256)
        F[x >> 7][x & 127] = feat[rbase * CC + x];
    __syncthreads();

    float aq[4], ak[4], av[4];
    #pragma unroll
    for (int r = 0; r < 4; r++) { aq[r] = bq[ch]; ak[r] = bk[ch]; av[r] = bv[ch]; }
    for (int cc = 0; cc < CC; cc++) {
        float wq = Wq[cc * CC + ch], wk = Wk[cc * CC + ch], wv = Wv[cc * CC + ch];
        #pragma unroll
        for (int r = 0; r < 4; r++) {
            float f = F[half * 4 + r][cc];
            aq[r] += f * wq; ak[r] += f * wk; av[r] += f * wv;
        }
    }
    const int h = ch >> 5, d = ch & 31;
    #pragma unroll
    for (int r = 0; r < 4; r++) {
        int bi = rbase + half * 4 + r; int b = bi >> 8, i = bi & 255;
        int o = ((b * HH + h) * NN + i) * DD + d;
        g_q[o] = aq[r]; g_v[o] = av[r];
        g_kT[((b * HH + h) * DD + d) * NN + i] = ak[r];
    }
    if (tid < 24) {
        int r = tid / 3, kd = tid % 3;
        int bi = rbase + r;
        float mx = -1e30f, mn = 1e30f;
        for (int cn = 0; cn < 8; cn++) {
            float v2 = corners[(bi * 8 + cn) * 3 + kd];
            mx = fmaxf(mx, v2); mn = fminf(mn, v2);
        }
        g_sizes[bi * 3 + kd] = mx - mn;
    }
}

// ---------------- kernel 2b: QK logits GEMM (scaled by LOG2E) ----------------
// grid (NN/16, HH, BB) = 512 blocks, 256 threads = j. 16-i tile in smem.
__global__ __launch_bounds__(256) void k_logits()
{
    const int i0 = blockIdx.x * 16;
    const int h = blockIdx.y;
    const int b = blockIdx.z;
    const int tid = threadIdx.x;
    __shared__ float4 sQt[16 * 8];   // [i][d4]

    if (tid < 128) {
        const float4* qp = (const float4*)(g_q + ((size_t)(b * HH + h) * NN + i0) * DD);
        sQt[tid] = qp[tid];
    }
    const int j = tid;
    float kr[DD];
    {
        const float* kT = g_kT + (size_t)(b * HH + h) * DD * NN + j;
        #pragma unroll
        for (int d = 0; d < DD; d++) kr[d] = kT[d * NN];
    }
    __syncthreads();
    const float SC = 0.17677669529663687f * LOG2E;  // 1/sqrt(32) * log2(e)
    float* lp = g_logits + ((size_t)(b * HH + h) * NN + i0) * NN + j;
    #pragma unroll 4
    for (int i = 0; i < 16; i++) {
        float dot = 0.f;
        #pragma unroll
        for (int d4 = 0; d4 < 8; d4++) {
            float4 qv = sQt[i * 8 + d4];
            dot += qv.x * kr[d4 * 4 + 0] + qv.y * kr[d4 * 4 + 1]
                 + qv.z * kr[d4 * 4 + 2] + qv.w * kr[d4 * 4 + 3];
        }
        lp[(size_t)i * NN] = dot * SC;
    }
}

// ---------------- kernel 3: fused main — 2 queries (i) per block ----------------
__global__ __launch_bounds__(256, 3) void k_main(
    const float* __restrict__ centers,
    const float* __restrict__ Wo,
    const float* __restrict__ bo,
    float* __restrict__ out)
{
    const int i0 = blockIdx.x * 2;
    const int b = blockIdx.y;
    const int tid = threadIdx.x;

    __shared__ float  sRow6[6 * TT];      // rows 0..5 x LOG2E (i-independent)
    __shared__ float  sRowI[2][3 * TT];   // per-i folded rows 6..8 x LOG2E
    __shared__ float  sC0[2][TT];         // per-i folded const x LOG2E
    __shared__ float4 sVb4[TT];           // raw
    __shared__ float  sWrbF[2][9 * HH];   // per-i folded bias rows x LOG2E
    __shared__ float  sCbF[2][HH];
    __shared__ float  sCtr[2][3], sSz[2][3];
    __shared__ float4 sE4[2][NN];
    __shared__ float  sRedS[2][32];
    __shared__ float  sAVf[2][8][CC];
    __shared__ float  sOF[2][CC];
    __shared__ float  sOP[2][2][CC];

    float* sE = (float*)sE4;

    const float* Mb = g_M + b * (GG * TT);

    // ---- phase A ----
    for (int x = tid; x < 6 * TT; x += 256) sRow6[x] = Mb[x] * LOG2E;
    ((float*)sVb4)[tid] = g_Vb[b * TT * HH + tid];
    if (tid < 12) {
        int ii = tid / 6, r = tid % 6;
        if (r < 3) sCtr[ii][r] = centers[(b * NN + i0 + ii) * 3 + r];
        else       sSz[ii][r - 3] = g_sizes[(b * NN + i0 + ii) * 3 + (r - 3)];
    }
    __syncthreads();

    // ---- phase B: fold i-side ----
    if (tid < 128) {
        const int ii = tid >> 6, t = tid & 63;
        float inv0 = __fdividef(1.f, sSz[ii][0] + FEPS);
        float inv1 = __fdividef(1.f, sSz[ii][1] + FEPS);
        float inv2 = __fdividef(1.f, sSz[ii][2] + FEPS);
        float m6 = Mb[6 * TT + t],  m7 = Mb[7 * TT + t],  m8 = Mb[8 * TT + t];
        float m9 = Mb[9 * TT + t], m10 = Mb[10 * TT + t], m11 = Mb[11 * TT + t];
        float c0 = g_c0[b * TT + t] * LOG2E
                 - sCtr[ii][0] * sRow6[0 * TT + t]
                 - sCtr[ii][1] * sRow6[1 * TT + t]
                 - sCtr[ii][2] * sRow6[2 * TT + t]
                 - (sSz[ii][0] * m6 + sSz[ii][1] * m7 + sSz[ii][2] * m8) * LOG2E;
        sC0[ii][t] = c0;
        sRowI[ii][0 * TT + t] = (m6 + inv0 * m9) * LOG2E;
        sRowI[ii][1 * TT + t] = (m7 + inv1 * m10) * LOG2E;
        sRowI[ii][2 * TT + t] = (m8 + inv2 * m11) * LOG2E;
    } else if (tid < 200) {
        const int q = tid - 128; const int ii = q / 36; const int qq = q % 36;
        const int g = qq >> 2, h = qq & 3;
        float w = g_Wrb[g * HH + h];
        if (g >= 6) {
            float invs = __fdividef(1.f, sSz[ii][g - 6] + FEPS);
            w += invs * g_Wrb[(g + 3) * HH + h];
        }
        sWrbF[ii][qq] = w * LOG2E;
    } else if (tid < 208) {
        const int q = tid - 200; const int ii = q >> 2, h = q & 3;
        float c = g_cb[h];
        #pragma unroll
        for (int kk = 0; kk < 3; kk++)
            c -= sCtr[ii][kk] * g_Wrb[kk * HH + h] + sSz[ii][kk] * g_Wrb[(6 + kk) * HH + h];
        sCbF[ii][h] = c * LOG2E;
    }
    __syncthreads();

    // ---- per-thread geometry (j = tid); cv0..2,6..8 shared across i ----
    const int j = tid;
    float cjx = centers[(b * NN + j) * 3 + 0];
    float cjy = centers[(b * NN + j) * 3 + 1];
    float cjz = centers[(b * NN + j) * 3 + 2];
    float sj0 = g_sizes[(b * NN + j) * 3 + 0];
    float sj1 = g_sizes[(b * NN + j) * 3 + 1];
    float sj2 = g_sizes[(b * NN + j) * 3 + 2];
    ull cvS[6];
    cvS[0] = pack2(cjx, cjx); cvS[1] = pack2(cjy, cjy); cvS[2] = pack2(cjz, cjz);
    cvS[3] = pack2(sj0, sj0); cvS[4] = pack2(sj1, sj1); cvS[5] = pack2(sj2, sj2);
    ull cvI[2][3];
    #pragma unroll
    for (int ii = 0; ii < 2; ii++) {
        float rx = cjx - sCtr[ii][0], ry = cjy - sCtr[ii][1], rz = cjz - sCtr[ii][2];
        float r2all = rx * rx + ry * ry + rz * rz;
        float r2h   = rx * rx + ry * ry;
        float dist  = r2all * rsqrtf(r2all + 1e-30f);
        float horiz = r2h * rsqrtf(r2h + 1e-30f);
        float dl = __logf(dist + FEPS);
        float ce = __fdividef(rz, dist + FEPS);
        cvI[ii][0] = pack2(dl, dl);
        cvI[ii][1] = pack2(horiz, horiz);
        cvI[ii][2] = pack2(ce, ce);
    }

    const uint32_t row6Addr = (uint32_t)__cvta_generic_to_shared(sRow6);
    const uint32_t rowIAddr0 = (uint32_t)__cvta_generic_to_shared(sRowI[0]);
    const uint32_t rowIAddr1 = (uint32_t)__cvta_generic_to_shared(sRowI[1]);
    const uint32_t c0Addr0 = (uint32_t)__cvta_generic_to_shared(sC0[0]);
    const uint32_t c0Addr1 = (uint32_t)__cvta_generic_to_shared(sC0[1]);
    const uint32_t vbAddr  = (uint32_t)__cvta_generic_to_shared(sVb4);
    const uint32_t wrbAddr = (uint32_t)__cvta_generic_to_shared(sWrbF);

    // ---- token scores + softmax accumulation for BOTH i ----
    float ssum[2] = {0.f, 0.f};
    ull aA[2] = {0ull, 0ull}, aB[2] = {0ull, 0ull};
    #pragma unroll
    for (int c = 0; c < 8; c++) {       // 8 chunks of 8 tokens
        ull s0[2][4];
        LDS2(s0[0][0], s0[0][1], c0Addr0 + c * 32);
        LDS2(s0[0][2], s0[0][3], c0Addr0 + c * 32 + 16);
        LDS2(s0[1][0], s0[1][1], c0Addr1 + c * 32);
        LDS2(s0[1][2], s0[1][3], c0Addr1 + c * 32 + 16);
        // shared rows 0..2 (centers_j), shared cv
        #pragma unroll
        for (int g = 0; g < 3; g++) {
            ull r0, r1, r2, r3;
            LDS2(r0, r1, row6Addr + g * 256 + c * 32);
            LDS2(r2, r3, row6Addr + g * 256 + c * 32 + 16);
            #pragma unroll
            for (int ii = 0; ii < 2; ii++) {
                s0[ii][0] = fma2(cvS[g], r0, s0[ii][0]);
                s0[ii][1] = fma2(cvS[g], r1, s0[ii][1]);
                s0[ii][2] = fma2(cvS[g], r2, s0[ii][2]);
                s0[ii][3] = fma2(cvS[g], r3, s0[ii][3]);
            }
        }
        // shared rows 3..5 (dl/horiz/ce rows), per-i cv
        #pragma unroll
        for (int g = 0; g < 3; g++) {
            ull r0, r1, r2, r3;
            LDS2(r0, r1, row6Addr + (g + 3) * 256 + c * 32);
            LDS2(r2, r3, row6Addr + (g + 3) * 256 + c * 32 + 16);
            #pragma unroll
            for (int ii = 0; ii < 2; ii++) {
                s0[ii][0] = fma2(cvI[ii][g], r0, s0[ii][0]);
                s0[ii][1] = fma2(cvI[ii][g], r1, s0[ii][1]);
                s0[ii][2] = fma2(cvI[ii][g], r2, s0[ii][2]);
                s0[ii][3] = fma2(cvI[ii][g], r3, s0[ii][3]);
            }
        }
        // per-i rows 6..8 (folded size rows), shared cv (size_j)
        #pragma unroll
        for (int g = 0; g < 3; g++) {
            ull r0, r1, r2, r3;
            LDS2(r0, r1, rowIAddr0 + g * 256 + c * 32);
            LDS2(r2, r3, rowIAddr0 + g * 256 + c * 32 + 16);
            s0[0][0] = fma2(cvS[3 + g], r0, s0[0][0]);
            s0[0][1] = fma2(cvS[3 + g], r1, s0[0][1]);
            s0[0][2] = fma2(cvS[3 + g], r2, s0[0][2]);
            s0[0][3] = fma2(cvS[3 + g], r3, s0[0][3]);
            LDS2(r0, r1, rowIAddr1 + g * 256 + c * 32);
            LDS2(r2, r3, rowIAddr1 + g * 256 + c * 32 + 16);
            s0[1][0] = fma2(cvS[3 + g], r0, s0[1][0]);
            s0[1][1] = fma2(cvS[3 + g], r1, s0[1][1]);
            s0[1][2] = fma2(cvS[3 + g], r2, s0[1][2]);
            s0[1][3] = fma2(cvS[3 + g], r3, s0[1][3]);
        }
        // exp + Vb accumulation; Vb loads shared by both i
        #pragma unroll
        for (int k = 0; k < 4; k++) {   // each k handles 2 tokens (one ull)
            int t0 = c * 8 + k * 2;
            ull vA0, vB0, vA1, vB1;
            LDS2(vA0, vB0, vbAddr + t0 * 16);
            LDS2(vA1, vB1, vbAddr + t0 * 16 + 16);
            #pragma unroll
            for (int ii = 0; ii < 2; ii++) {
                float2 v = unpack2(s0[ii][k]);
                float e0 = ex2(v.x);
                float e1 = ex2(v.y);
                ssum[ii] += e0 + e1;
                ull e02 = pack2(e0, e0);
                ull e12 = pack2(e1, e1);
                aA[ii] = fma2(e02, vA0, aA[ii]); aB[ii] = fma2(e02, vB0, aB[ii]);
                aA[ii] = fma2(e12, vA1, aA[ii]); aB[ii] = fma2(e12, vB1, aB[ii]);
            }
        }
    }

    // ---- bias matvec + logits + exp for both i ----
    #pragma unroll
    for (int ii = 0; ii < 2; ii++) {
        ull bA = pack2(sCbF[ii][0], sCbF[ii][1]);
        ull bB = pack2(sCbF[ii][2], sCbF[ii][3]);
        const uint32_t wa = wrbAddr + ii * (9 * HH * 4);
        ull wA, wB;
        LDS2(wA, wB, wa + 0 * 16);  bA = fma2(cvS[0], wA, bA); bB = fma2(cvS[0], wB, bB);
        LDS2(wA, wB, wa + 1 * 16);  bA = fma2(cvS[1], wA, bA); bB = fma2(cvS[1], wB, bB);
        LDS2(wA, wB, wa + 2 * 16);  bA = fma2(cvS[2], wA, bA); bB = fma2(cvS[2], wB, bB);
        LDS2(wA, wB, wa + 3 * 16);  bA = fma2(cvI[ii][0], wA, bA); bB = fma2(cvI[ii][0], wB, bB);
        LDS2(wA, wB, wa + 4 * 16);  bA = fma2(cvI[ii][1], wA, bA); bB = fma2(cvI[ii][1], wB, bB);
        LDS2(wA, wB, wa + 5 * 16);  bA = fma2(cvI[ii][2], wA, bA); bB = fma2(cvI[ii][2], wB, bB);
        LDS2(wA, wB, wa + 6 * 16);  bA = fma2(cvS[3], wA, bA); bB = fma2(cvS[3], wB, bB);
        LDS2(wA, wB, wa + 7 * 16);  bA = fma2(cvS[4], wA, bA); bB = fma2(cvS[4], wB, bB);
        LDS2(wA, wB, wa + 8 * 16);  bA = fma2(cvS[5], wA, bA); bB = fma2(cvS[5], wB, bB);
        float2 b01 = unpack2(bA), b23 = unpack2(bB);
        float inv = __fdividef(1.f, ssum[ii]);
        float invL = inv * LOG2E;
        float2 a01 = unpack2(aA[ii]), a23 = unpack2(aB[ii]);
        const float* lp = g_logits + ((size_t)(b * HH) * NN + (i0 + ii)) * NN + j;
        float e0 = ex2(lp[0]                   + b01.x + a01.x * invL);
        float e1 = ex2(lp[(size_t)NN * NN]     + b01.y + a01.y * invL);
        float e2 = ex2(lp[(size_t)2 * NN * NN] + b23.x + a23.x * invL);
        float e3 = ex2(lp[(size_t)3 * NN * NN] + b23.y + a23.y * invL);
        sE4[ii][tid] = make_float4(e0, e1, e2, e3);
        // warp sum reduce
        float s4[HH] = {e0, e1, e2, e3};
        #pragma unroll
        for (int off = 16; off; off >>= 1) {
            #pragma unroll
            for (int h = 0; h < HH; h++)
                s4[h] += __shfl_xor_sync(0xffffffffu, s4[h], off);
        }
        if ((tid & 31) == 0) {
            #pragma unroll
            for (int h = 0; h < HH; h++) sRedS[ii][(tid >> 5) * 4 + h] = s4[h];
        }
    }
    __syncthreads();

    // ---- AV: shared V loads feed both i ----
    const int wid = tid >> 5, lane = tid & 31;
    {
        const int h = lane >> 3, d4 = lane & 7;
        const float* vp = g_v + (size_t)(b * HH + h) * NN * DD + d4 * 4;
        ull acc[2][2] = {{0ull, 0ull}, {0ull, 0ull}};
        #pragma unroll 8
        for (int jj = 0; jj < 32; jj++) {
            int j2 = wid * 32 + jj;
            ull vA, vB;
            LDG2(vA, vB, vp + (size_t)j2 * DD);
            #pragma unroll
            for (int ii = 0; ii < 2; ii++) {
                float e = sE[ii * (NN * 4) + j2 * 4 + h];
                ull e2 = pack2(e, e);
                acc[ii][0] = fma2(e2, vA, acc[ii][0]);
                acc[ii][1] = fma2(e2, vB, acc[ii][1]);
            }
        }
        #pragma unroll
        for (int ii = 0; ii < 2; ii++) {
            ull* dst = (ull*)&sAVf[ii][wid][lane * 4];
            dst[0] = acc[ii][0]; dst[1] = acc[ii][1];
        }
    }
    __syncthreads();
    {
        const int ii = tid >> 7, c = tid & 127;
        const int h = c >> 5, d = c & 31;
        float s = 0.f;
        #pragma unroll
        for (int w = 0; w < 8; w++) s += sAVf[ii][w][h * 32 + d];
        float denom = sRedS[ii][h];
        #pragma unroll
        for (int w = 1; w < 8; w++) denom += sRedS[ii][w * 4 + h];
        sOF[ii][c] = __fdividef(s, denom);
    }
    __syncthreads();

    // ---- output projection: Wo loads shared by both i ----
    {
        const int c = tid & 127;
        const int half = tid >> 7;
        const float* wp = Wo + (half * 64) * CC + c;
        float a0 = 0.f, a1 = 0.f;
        #pragma unroll 8
        for (int cc2 = 0; cc2 < 64; cc2++) {
            float w = wp[cc2 * CC];
            a0 += sOF[0][half * 64 + cc2] * w;
            a1 += sOF[1][half * 64 + cc2] * w;
        }
        sOP[0][half][c] = a0;
        sOP[1][half][c] = a1;
    }
    __syncthreads();
    {
        const int ii = tid >> 7, c = tid & 127;
        out[(b * NN + i0 + ii) * CC + c] = bo[c] + sOP[ii][0][c] + sOP[ii][1][c];
    }
}

// ---------------- launch ----------------
extern "C" void kernel_launch(void* const* d_in, const int* in_sizes, int n_in,
                              void* d_out, int out_size)
{
    const float* feat    = (const float*)d_in[0];
    const float* centers = (const float*)d_in[1];
    const float* corners = (const float*)d_in[2];
    const float* lang    = (const float*)d_in[3];
    const float* Wq    = (const float*)d_in[4];
    const float* bq    = (const float*)d_in[5];
    const float* Wk    = (const float*)d_in[6];
    const float* bk    = (const float*)d_in[7];
    const float* Wv    = (const float*)d_in[8];
    const float* bv    = (const float*)d_in[9];
    const float* Wo    = (const float*)d_in[10];
    const float* bo    = (const float*)d_in[11];
    const float* Wrel  = (const float*)d_in[12];
    const float* brel  = (const float*)d_in[13];
    const float* Wtk   = (const float*)d_in[14];
    const float* btk   = (const float*)d_in[15];
    const float* Wtv   = (const float*)d_in[16];
    const float* btv   = (const float*)d_in[17];
    const float* Wbias = (const float*)d_in[18];
    const float* bbias = (const float*)d_in[19];

    k_combos<<<9, 256>>>(Wtk, btk, Wtv, btv, Wrel, brel, Wbias, bbias);
    k_lang<<<BB * TT, 128>>>(lang);
    k_qkv<<<BB * NN / 8, 256>>>(feat, corners, Wq, bq, Wk, bk, Wv, bv);
    k_logits<<<dim3(NN / 16, HH, BB), 256>>>();
    k_main<<<dim3(NN / 2, BB), 256>>>(centers, Wo, bo, (float*)d_out);
}

// round 8
// speedup vs baseline: 2.1495x; 1.0184x over previous
#include <cuda_runtime.h>
#include <math.h>
#include <stdint.h>

#define BB 8
#define NN 256
#define CC 128
#define TT 64
#define HH 4
#define GG 12
#define DD 32
#define FEPS 1e-6f
#define LOG2E 1.4426950408889634f

typedef unsigned long long ull;

// ---- f32x2 packed-math helpers ----
__device__ __forceinline__ ull pack2(float lo, float hi) {
    ull d;
    asm("mov.b64 %0, {%1, %2};" : "=l"(d)
        : "r"(__float_as_uint(lo)), "r"(__float_as_uint(hi)));
    return d;
}
__device__ __forceinline__ float2 unpack2(ull s) {
    uint32_t a, b;
    asm("mov.b64 {%0, %1}, %2;" : "=r"(a), "=r"(b) : "l"(s));
    return make_float2(__uint_as_float(a), __uint_as_float(b));
}
__device__ __forceinline__ ull fma2(ull a, ull b, ull c) {
    ull d;
    asm("fma.rn.f32x2 %0, %1, %2, %3;" : "=l"(d) : "l"(a), "l"(b), "l"(c));
    return d;
}
__device__ __forceinline__ float ex2(float x) {
    float y;
    asm("ex2.approx.ftz.f32 %0, %1;" : "=f"(y) : "f"(x));
    return y;
}
#define LDS2(a, b, addr) \
    asm volatile("ld.shared.v2.u64 {%0, %1}, [%2];" : "=l"(a), "=l"(b) : "r"(addr))
#define LDG2(a, b, p) \
    asm volatile("ld.global.nc.v2.u64 {%0, %1}, [%2];" : "=l"(a), "=l"(b) : "l"(p))

// ---------------- scratch ----------------
__device__ float g_P[CC * GG];
__device__ float g_p0[GG];
__device__ float g_pc[CC];
__device__ float g_pc0[1];
__device__ float g_Qm[CC * HH];
__device__ float g_q0[HH];
__device__ float g_Wrb[GG * HH];
__device__ float g_cb[HH];
__device__ float g_M[BB * GG * TT];
__device__ float g_c0[BB * TT];
__device__ float g_Vb[BB * TT * HH];
__device__ float g_q[BB * HH * NN * DD];
__device__ float g_kT[BB * HH * DD * NN];      // [b][h][d][j]
__device__ float g_v[BB * HH * NN * DD];
__device__ float g_sizes[BB * NN * 3];
__device__ float g_logits[BB * HH * NN * NN];  // [b][h][i][j] (scaled QK * LOG2E)

// ---------------- kernel 0: weight combos ----------------
__global__ void k_combos(const float* __restrict__ Wtk, const float* __restrict__ btk,
                         const float* __restrict__ Wtv, const float* __restrict__ btv,
                         const float* __restrict__ Wrel, const float* __restrict__ brel,
                         const float* __restrict__ Wbias, const float* __restrict__ bbias)
{
    const float isC = 0.08838834764831845f;  // 1/sqrt(128)
    int idx = blockIdx.x * blockDim.x + threadIdx.x;
    if (idx < 1536) {
        int cc = idx / 12, g = idx % 12;
        float s = 0.f;
        for (int c = 0; c < CC; c++) s += Wtk[cc * CC + c] * Wrel[g * CC + c];
        g_P[idx] = s * isC;
    } else if (idx < 1548) {
        int g = idx - 1536;
        float s = 0.f;
        for (int c = 0; c < CC; c++) s += btk[c] * Wrel[g * CC + c];
        g_p0[g] = s * isC;
    } else if (idx < 1676) {
        int cc = idx - 1548;
        float s = 0.f;
        for (int c = 0; c < CC; c++) s += Wtk[cc * CC + c] * brel[c];
        g_pc[cc] = s * isC;
    } else if (idx == 1676) {
        float s = 0.f;
        for (int c = 0; c < CC; c++) s += btk[c] * brel[c];
        g_pc0[0] = s * isC;
    } else if (idx < 2189) {
        int q = idx - 1677; int cc = q / 4, h = q % 4;
        float s = 0.f;
        for (int c = 0; c < CC; c++) s += Wtv[cc * CC + c] * Wbias[c * HH + h];
        g_Qm[cc * HH + h] = s;
    } else if (idx < 2193) {
        int h = idx - 2189;
        float s = 0.f;
        for (int c = 0; c < CC; c++) s += btv[c] * Wbias[c * HH + h];
        g_q0[h] = s;
    } else if (idx < 2241) {
        int q = idx - 2193; int g = q / 4, h = q % 4;
        float s = 0.f;
        for (int c = 0; c < CC; c++) s += Wrel[g * CC + c] * Wbias[c * HH + h];
        g_Wrb[q] = s;
    } else if (idx < 2245) {
        int h = idx - 2241;
        float s = 0.f;
        for (int c = 0; c < CC; c++) s += brel[c] * Wbias[c * HH + h];
        g_cb[h] = s + bbias[h];
    }
}

// ---------------- kernel 1: lang tokens -> M, c0, Vb ----------------
__global__ __launch_bounds__(128) void k_lang(const float* __restrict__ lang)
{
    const int bt = blockIdx.x;
    const int b = bt >> 6, t = bt & 63;
    const int tid = threadIdx.x;
    __shared__ float L[CC];
    L[tid] = lang[bt * CC + tid];
    __syncthreads();
    const int wid = tid >> 5, lane = tid & 31;
    for (int o = wid; o < 17; o += 4) {
        float s = 0.f;
        if (o < 12) {
            for (int c = lane; c < CC; c += 32) s += L[c] * g_P[c * GG + o];
        } else if (o == 12) {
            for (int c = lane; c < CC; c += 32) s += L[c] * g_pc[c];
        } else {
            int h = o - 13;
            for (int c = lane; c < CC; c += 32) s += L[c] * g_Qm[c * HH + h];
        }
        #pragma unroll
        for (int off = 16; off; off >>= 1) s += __shfl_xor_sync(0xffffffffu, s, off);
        if (lane == 0) {
            if (o < 12)       g_M[(b * GG + o) * TT + t] = s + g_p0[o];
            else if (o == 12) g_c0[b * TT + t] = s + g_pc0[0];
            else              g_Vb[(b * TT + t) * HH + (o - 13)] = s + g_q0[o - 13];
        }
    }
}

// ---------------- kernel 2: QKV projections + box sizes ----------------
__global__ __launch_bounds__(256) void k_qkv(
    const float* __restrict__ feat, const float* __restrict__ corners,
    const float* __restrict__ Wq, const float* __restrict__ bq,
    const float* __restrict__ Wk, const float* __restrict__ bk,
    const float* __restrict__ Wv, const float* __restrict__ bv)
{
    const int blk = blockIdx.x;
    const int tid = threadIdx.x;
    const int half = tid >> 7;
    const int ch = tid & 127;
    const int rbase = blk * 8;
    __shared__ float F[8][CC];
    for (int x = tid; x < 8 * CC; x += 256)
        F[x >> 7][x & 127] = feat[rbase * CC + x];
    __syncthreads();

    float aq[4], ak[4], av[4];
    #pragma unroll
    for (int r = 0; r < 4; r++) { aq[r] = bq[ch]; ak[r] = bk[ch]; av[r] = bv[ch]; }
    for (int cc = 0; cc < CC; cc++) {
        float wq = Wq[cc * CC + ch], wk = Wk[cc * CC + ch], wv = Wv[cc * CC + ch];
        #pragma unroll
        for (int r = 0; r < 4; r++) {
            float f = F[half * 4 + r][cc];
            aq[r] += f * wq; ak[r] += f * wk; av[r] += f * wv;
        }
    }
    const int h = ch >> 5, d = ch & 31;
    #pragma unroll
    for (int r = 0; r < 4; r++) {
        int bi = rbase + half * 4 + r; int b = bi >> 8, i = bi & 255;
        int o = ((b * HH + h) * NN + i) * DD + d;
        g_q[o] = aq[r]; g_v[o] = av[r];
        g_kT[((b * HH + h) * DD + d) * NN + i] = ak[r];
    }
    if (tid < 24) {
        int r = tid / 3, kd = tid % 3;
        int bi = rbase + r;
        float mx = -1e30f, mn = 1e30f;
        for (int cn = 0; cn < 8; cn++) {
            float v2 = corners[(bi * 8 + cn) * 3 + kd];
            mx = fmaxf(mx, v2); mn = fminf(mn, v2);
        }
        g_sizes[bi * 3 + kd] = mx - mn;
    }
}

// ---------------- kernel 2b: QK logits GEMM — i-pair packed FMA2 ----------------
// grid (NN/16, HH, BB), 256 threads = j. 16 i-rows = 8 packed pairs.
__global__ __launch_bounds__(256) void k_logits()
{
    const int i0 = blockIdx.x * 16;
    const int h = blockIdx.y;
    const int b = blockIdx.z;
    const int tid = threadIdx.x;
    __shared__ ull sQp[8][DD];   // [ipair][d] = (q_{i0+2p}[d], q_{i0+2p+1}[d])

    {
        const int p = tid >> 5, d = tid & 31;
        const float* qp_ = g_q + ((size_t)(b * HH + h) * NN + i0 + 2 * p) * DD + d;
        sQp[p][d] = pack2(qp_[0], qp_[DD]);
    }
    const int j = tid;
    ull kr2[DD];
    {
        const float* kT = g_kT + (size_t)(b * HH + h) * DD * NN + j;
        #pragma unroll
        for (int d = 0; d < DD; d++) { float kv = kT[d * NN]; kr2[d] = pack2(kv, kv); }
    }
    __syncthreads();
    const float SC = 0.17677669529663687f * LOG2E;  // 1/sqrt(32) * log2(e)
    float* lp = g_logits + ((size_t)(b * HH + h) * NN + i0) * NN + j;
    const uint32_t qAddr = (uint32_t)__cvta_generic_to_shared(sQp);
    #pragma unroll
    for (int pp = 0; pp < 4; pp++) {    // 2 pairs per iteration for ILP
        ull acc0 = 0ull, acc1 = 0ull;
        #pragma unroll
        for (int d2 = 0; d2 < DD / 2; d2++) {
            ull qa, qb;
            LDS2(qa, qb, qAddr + ((2 * pp) * DD + d2 * 2) * 8);
            acc0 = fma2(kr2[d2 * 2], qa, acc0);
            acc0 = fma2(kr2[d2 * 2 + 1], qb, acc0);
            LDS2(qa, qb, qAddr + ((2 * pp + 1) * DD + d2 * 2) * 8);
            acc1 = fma2(kr2[d2 * 2], qa, acc1);
            acc1 = fma2(kr2[d2 * 2 + 1], qb, acc1);
        }
        float2 r0 = unpack2(acc0), r1 = unpack2(acc1);
        lp[(size_t)(4 * pp + 0) * NN] = r0.x * SC;
        lp[(size_t)(4 * pp + 1) * NN] = r0.y * SC;
        lp[(size_t)(4 * pp + 2) * NN] = r1.x * SC;
        lp[(size_t)(4 * pp + 3) * NN] = r1.y * SC;
    }
}

// ---------------- kernel 3: fused main — 2 queries/block, no shuffle trees ----------------
__global__ __launch_bounds__(256, 3) void k_main(
    const float* __restrict__ centers,
    const float* __restrict__ Wo,
    const float* __restrict__ bo,
    float* __restrict__ out)
{
    const int i0 = blockIdx.x * 2;
    const int b = blockIdx.y;
    const int tid = threadIdx.x;

    __shared__ float  sRow6[6 * TT];      // rows 0..5 x LOG2E (i-independent)
    __shared__ float  sRowI[2][3 * TT];   // per-i folded rows 6..8 x LOG2E
    __shared__ float  sC0[2][TT];         // per-i folded const x LOG2E
    __shared__ float4 sVb4[TT];           // raw
    __shared__ float  sWrbF[2][9 * HH];   // per-i folded bias rows x LOG2E
    __shared__ float  sCbF[2][HH];
    __shared__ float  sCtr[2][3], sSz[2][3];
    __shared__ float4 sE4[2][NN];
    __shared__ float  sESum[2][8][HH];    // per-warp partial e-sums
    __shared__ float  sAVf[2][8][CC];
    __shared__ float  sOFi[CC * 2];       // normalized AV, interleaved [c][ii]
    __shared__ float  sOP[2][2][CC];

    float* sE = (float*)sE4;

    const float* Mb = g_M + b * (GG * TT);

    // ---- phase A ----
    for (int x = tid; x < 6 * TT; x += 256) sRow6[x] = Mb[x] * LOG2E;
    ((float*)sVb4)[tid] = g_Vb[b * TT * HH + tid];
    if (tid < 12) {
        int ii = tid / 6, r = tid % 6;
        if (r < 3) sCtr[ii][r] = centers[(b * NN + i0 + ii) * 3 + r];
        else       sSz[ii][r - 3] = g_sizes[(b * NN + i0 + ii) * 3 + (r - 3)];
    }
    __syncthreads();

    // ---- phase B: fold i-side ----
    if (tid < 128) {
        const int ii = tid >> 6, t = tid & 63;
        float inv0 = __fdividef(1.f, sSz[ii][0] + FEPS);
        float inv1 = __fdividef(1.f, sSz[ii][1] + FEPS);
        float inv2 = __fdividef(1.f, sSz[ii][2] + FEPS);
        float m6 = Mb[6 * TT + t],  m7 = Mb[7 * TT + t],  m8 = Mb[8 * TT + t];
        float m9 = Mb[9 * TT + t], m10 = Mb[10 * TT + t], m11 = Mb[11 * TT + t];
        float c0 = g_c0[b * TT + t] * LOG2E
                 - sCtr[ii][0] * sRow6[0 * TT + t]
                 - sCtr[ii][1] * sRow6[1 * TT + t]
                 - sCtr[ii][2] * sRow6[2 * TT + t]
                 - (sSz[ii][0] * m6 + sSz[ii][1] * m7 + sSz[ii][2] * m8) * LOG2E;
        sC0[ii][t] = c0;
        sRowI[ii][0 * TT + t] = (m6 + inv0 * m9) * LOG2E;
        sRowI[ii][1 * TT + t] = (m7 + inv1 * m10) * LOG2E;
        sRowI[ii][2 * TT + t] = (m8 + inv2 * m11) * LOG2E;
    } else if (tid < 200) {
        const int q = tid - 128; const int ii = q / 36; const int qq = q % 36;
        const int g = qq >> 2, h = qq & 3;
        float w = g_Wrb[g * HH + h];
        if (g >= 6) {
            float invs = __fdividef(1.f, sSz[ii][g - 6] + FEPS);
            w += invs * g_Wrb[(g + 3) * HH + h];
        }
        sWrbF[ii][qq] = w * LOG2E;
    } else if (tid < 208) {
        const int q = tid - 200; const int ii = q >> 2, h = q & 3;
        float c = g_cb[h];
        #pragma unroll
        for (int kk = 0; kk < 3; kk++)
            c -= sCtr[ii][kk] * g_Wrb[kk * HH + h] + sSz[ii][kk] * g_Wrb[(6 + kk) * HH + h];
        sCbF[ii][h] = c * LOG2E;
    }
    __syncthreads();

    // ---- per-thread geometry (j = tid) ----
    const int j = tid;
    float cjx = centers[(b * NN + j) * 3 + 0];
    float cjy = centers[(b * NN + j) * 3 + 1];
    float cjz = centers[(b * NN + j) * 3 + 2];
    float sj0 = g_sizes[(b * NN + j) * 3 + 0];
    float sj1 = g_sizes[(b * NN + j) * 3 + 1];
    float sj2 = g_sizes[(b * NN + j) * 3 + 2];
    ull cvS[6];
    cvS[0] = pack2(cjx, cjx); cvS[1] = pack2(cjy, cjy); cvS[2] = pack2(cjz, cjz);
    cvS[3] = pack2(sj0, sj0); cvS[4] = pack2(sj1, sj1); cvS[5] = pack2(sj2, sj2);
    ull cvI[2][3];
    #pragma unroll
    for (int ii = 0; ii < 2; ii++) {
        float rx = cjx - sCtr[ii][0], ry = cjy - sCtr[ii][1], rz = cjz - sCtr[ii][2];
        float r2all = rx * rx + ry * ry + rz * rz;
        float r2h   = rx * rx + ry * ry;
        float dist  = r2all * rsqrtf(r2all + 1e-30f);
        float horiz = r2h * rsqrtf(r2h + 1e-30f);
        float dl = __logf(dist + FEPS);
        float ce = __fdividef(rz, dist + FEPS);
        cvI[ii][0] = pack2(dl, dl);
        cvI[ii][1] = pack2(horiz, horiz);
        cvI[ii][2] = pack2(ce, ce);
    }

    const uint32_t row6Addr = (uint32_t)__cvta_generic_to_shared(sRow6);
    const uint32_t rowIAddr0 = (uint32_t)__cvta_generic_to_shared(sRowI[0]);
    const uint32_t rowIAddr1 = (uint32_t)__cvta_generic_to_shared(sRowI[1]);
    const uint32_t c0Addr0 = (uint32_t)__cvta_generic_to_shared(sC0[0]);
    const uint32_t c0Addr1 = (uint32_t)__cvta_generic_to_shared(sC0[1]);
    const uint32_t vbAddr  = (uint32_t)__cvta_generic_to_shared(sVb4);
    const uint32_t wrbAddr = (uint32_t)__cvta_generic_to_shared(sWrbF);

    // ---- token scores + softmax accumulation for BOTH i ----
    float ssum[2] = {0.f, 0.f};
    ull aA[2] = {0ull, 0ull}, aB[2] = {0ull, 0ull};
    #pragma unroll
    for (int c = 0; c < 8; c++) {       // 8 chunks of 8 tokens
        ull s0[2][4];
        LDS2(s0[0][0], s0[0][1], c0Addr0 + c * 32);
        LDS2(s0[0][2], s0[0][3], c0Addr0 + c * 32 + 16);
        LDS2(s0[1][0], s0[1][1], c0Addr1 + c * 32);
        LDS2(s0[1][2], s0[1][3], c0Addr1 + c * 32 + 16);
        #pragma unroll
        for (int g = 0; g < 3; g++) {
            ull r0, r1, r2, r3;
            LDS2(r0, r1, row6Addr + g * 256 + c * 32);
            LDS2(r2, r3, row6Addr + g * 256 + c * 32 + 16);
            #pragma unroll
            for (int ii = 0; ii < 2; ii++) {
                s0[ii][0] = fma2(cvS[g], r0, s0[ii][0]);
                s0[ii][1] = fma2(cvS[g], r1, s0[ii][1]);
                s0[ii][2] = fma2(cvS[g], r2, s0[ii][2]);
                s0[ii][3] = fma2(cvS[g], r3, s0[ii][3]);
            }
        }
        #pragma unroll
        for (int g = 0; g < 3; g++) {
            ull r0, r1, r2, r3;
            LDS2(r0, r1, row6Addr + (g + 3) * 256 + c * 32);
            LDS2(r2, r3, row6Addr + (g + 3) * 256 + c * 32 + 16);
            #pragma unroll
            for (int ii = 0; ii < 2; ii++) {
                s0[ii][0] = fma2(cvI[ii][g], r0, s0[ii][0]);
                s0[ii][1] = fma2(cvI[ii][g], r1, s0[ii][1]);
                s0[ii][2] = fma2(cvI[ii][g], r2, s0[ii][2]);
                s0[ii][3] = fma2(cvI[ii][g], r3, s0[ii][3]);
            }
        }
        #pragma unroll
        for (int g = 0; g < 3; g++) {
            ull r0, r1, r2, r3;
            LDS2(r0, r1, rowIAddr0 + g * 256 + c * 32);
            LDS2(r2, r3, rowIAddr0 + g * 256 + c * 32 + 16);
            s0[0][0] = fma2(cvS[3 + g], r0, s0[0][0]);
            s0[0][1] = fma2(cvS[3 + g], r1, s0[0][1]);
            s0[0][2] = fma2(cvS[3 + g], r2, s0[0][2]);
            s0[0][3] = fma2(cvS[3 + g], r3, s0[0][3]);
            LDS2(r0, r1, rowIAddr1 + g * 256 + c * 32);
            LDS2(r2, r3, rowIAddr1 + g * 256 + c * 32 + 16);
            s0[1][0] = fma2(cvS[3 + g], r0, s0[1][0]);
            s0[1][1] = fma2(cvS[3 + g], r1, s0[1][1]);
            s0[1][2] = fma2(cvS[3 + g], r2, s0[1][2]);
            s0[1][3] = fma2(cvS[3 + g], r3, s0[1][3]);
        }
        #pragma unroll
        for (int k = 0; k < 4; k++) {   // each k handles 2 tokens
            int t0 = c * 8 + k * 2;
            ull vA0, vB0, vA1, vB1;
            LDS2(vA0, vB0, vbAddr + t0 * 16);
            LDS2(vA1, vB1, vbAddr + t0 * 16 + 16);
            #pragma unroll
            for (int ii = 0; ii < 2; ii++) {
                float2 v = unpack2(s0[ii][k]);
                float e0 = ex2(v.x);
                float e1 = ex2(v.y);
                ssum[ii] += e0 + e1;
                ull e02 = pack2(e0, e0);
                ull e12 = pack2(e1, e1);
                aA[ii] = fma2(e02, vA0, aA[ii]); aB[ii] = fma2(e02, vB0, aB[ii]);
                aA[ii] = fma2(e12, vA1, aA[ii]); aB[ii] = fma2(e12, vB1, aB[ii]);
            }
        }
    }

    // ---- bias matvec + logits + exp for both i (no reductions here) ----
    #pragma unroll
    for (int ii = 0; ii < 2; ii++) {
        ull bA = pack2(sCbF[ii][0], sCbF[ii][1]);
        ull bB = pack2(sCbF[ii][2], sCbF[ii][3]);
        const uint32_t wa = wrbAddr + ii * (9 * HH * 4);
        ull wA, wB;
        LDS2(wA, wB, wa + 0 * 16);  bA = fma2(cvS[0], wA, bA); bB = fma2(cvS[0], wB, bB);
        LDS2(wA, wB, wa + 1 * 16);  bA = fma2(cvS[1], wA, bA); bB = fma2(cvS[1], wB, bB);
        LDS2(wA, wB, wa + 2 * 16);  bA = fma2(cvS[2], wA, bA); bB = fma2(cvS[2], wB, bB);
        LDS2(wA, wB, wa + 3 * 16);  bA = fma2(cvI[ii][0], wA, bA); bB = fma2(cvI[ii][0], wB, bB);
        LDS2(wA, wB, wa + 4 * 16);  bA = fma2(cvI[ii][1], wA, bA); bB = fma2(cvI[ii][1], wB, bB);
        LDS2(wA, wB, wa + 5 * 16);  bA = fma2(cvI[ii][2], wA, bA); bB = fma2(cvI[ii][2], wB, bB);
        LDS2(wA, wB, wa + 6 * 16);  bA = fma2(cvS[3], wA, bA); bB = fma2(cvS[3], wB, bB);
        LDS2(wA, wB, wa + 7 * 16);  bA = fma2(cvS[4], wA, bA); bB = fma2(cvS[4], wB, bB);
        LDS2(wA, wB, wa + 8 * 16);  bA = fma2(cvS[5], wA, bA); bB = fma2(cvS[5], wB, bB);
        float2 b01 = unpack2(bA), b23 = unpack2(bB);
        float inv = __fdividef(1.f, ssum[ii]);
        float invL = inv * LOG2E;
        float2 a01 = unpack2(aA[ii]), a23 = unpack2(aB[ii]);
        const float* lp = g_logits + ((size_t)(b * HH) * NN + (i0 + ii)) * NN + j;
        float e0 = ex2(lp[0]                   + b01.x + a01.x * invL);
        float e1 = ex2(lp[(size_t)NN * NN]     + b01.y + a01.y * invL);
        float e2 = ex2(lp[(size_t)2 * NN * NN] + b23.x + a23.x * invL);
        float e3 = ex2(lp[(size_t)3 * NN * NN] + b23.y + a23.y * invL);
        sE4[ii][tid] = make_float4(e0, e1, e2, e3);
    }
    __syncthreads();

    // ---- AV: shared V loads feed both i; e-sums folded in ----
    const int wid = tid >> 5, lane = tid & 31;
    {
        const int h = lane >> 3, d4 = lane & 7;
        const float* vp = g_v + (size_t)(b * HH + h) * NN * DD + d4 * 4;
        ull acc[2][2] = {{0ull, 0ull}, {0ull, 0ull}};
        float eacc[2] = {0.f, 0.f};
        #pragma unroll 8
        for (int jj = 0; jj < 32; jj++) {
            int j2 = wid * 32 + jj;
            ull vA, vB;
            LDG2(vA, vB, vp + (size_t)j2 * DD);
            #pragma unroll
            for (int ii = 0; ii < 2; ii++) {
                float e = sE[ii * (NN * 4) + j2 * 4 + h];
                eacc[ii] += e;
                ull e2 = pack2(e, e);
                acc[ii][0] = fma2(e2, vA, acc[ii][0]);
                acc[ii][1] = fma2(e2, vB, acc[ii][1]);
            }
        }
        #pragma unroll
        for (int ii = 0; ii < 2; ii++) {
            ull* dst = (ull*)&sAVf[ii][wid][lane * 4];
            dst[0] = acc[ii][0]; dst[1] = acc[ii][1];
        }
        if (d4 == 0) {
            sESum[0][wid][h] = eacc[0];
            sESum[1][wid][h] = eacc[1];
        }
    }
    __syncthreads();
    {
        const int ii = tid >> 7, c = tid & 127;
        const int h = c >> 5, d = c & 31;
        float s = 0.f;
        float denom = 0.f;
        #pragma unroll
        for (int w = 0; w < 8; w++) {
            s += sAVf[ii][w][h * 32 + d];
            denom += sESum[ii][w][h];
        }
        sOFi[c * 2 + ii] = __fdividef(s, denom);
    }
    __syncthreads();

    // ---- output projection: packed (ii0,ii1) fma2, Wo loads shared ----
    {
        const int c = tid & 127;
        const int half = tid >> 7;
        const float* wp = Wo + (half * 64) * CC + c;
        const uint32_t ofAddr = (uint32_t)__cvta_generic_to_shared(sOFi) + half * 64 * 8;
        ull acc2 = 0ull;
        #pragma unroll 8
        for (int cc2 = 0; cc2 < 64; cc2++) {
            float w = wp[cc2 * CC];
            ull o2;
            asm volatile("ld.shared.u64 %0, [%1];" : "=l"(o2) : "r"(ofAddr + cc2 * 8));
            acc2 = fma2(o2, pack2(w, w), acc2);
        }
        float2 r = unpack2(acc2);
        sOP[0][half][c] = r.x;
        sOP[1][half][c] = r.y;
    }
    __syncthreads();
    {
        const int ii = tid >> 7, c = tid & 127;
        out[(b * NN + i0 + ii) * CC + c] = bo[c] + sOP[ii][0][c] + sOP[ii][1][c];
    }
}

// ---------------- launch ----------------
extern "C" void kernel_launch(void* const* d_in, const int* in_sizes, int n_in,
                              void* d_out, int out_size)
{
    const float* feat    = (const float*)d_in[0];
    const float* centers = (const float*)d_in[1];
    const float* corners = (const float*)d_in[2];
    const float* lang    = (const float*)d_in[3];
    const float* Wq    = (const float*)d_in[4];
    const float* bq    = (const float*)d_in[5];
    const float* Wk    = (const float*)d_in[6];
    const float* bk    = (const float*)d_in[7];
    const float* Wv    = (const float*)d_in[8];
    const float* bv    = (const float*)d_in[9];
    const float* Wo    = (const float*)d_in[10];
    const float* bo    = (const float*)d_in[11];
    const float* Wrel  = (const float*)d_in[12];
    const float* brel  = (const float*)d_in[13];
    const float* Wtk   = (const float*)d_in[14];
    const float* btk   = (const float*)d_in[15];
    const float* Wtv   = (const float*)d_in[16];
    const float* btv   = (const float*)d_in[17];
    const float* Wbias = (const float*)d_in[18];
    const float* bbias = (const float*)d_in[19];

    k_combos<<<9, 256>>>(Wtk, btk, Wtv, btv, Wrel, brel, Wbias, bbias);
    k_lang<<<BB * TT, 128>>>(lang);
    k_qkv<<<BB * NN / 8, 256>>>(feat, corners, Wq, bq, Wk, bk, Wv, bv);
    k_logits<<<dim3(NN / 16, HH, BB), 256>>>();
    k_main<<<dim3(NN / 2, BB), 256>>>(centers, Wo, bo, (float*)d_out);
}